// round 11
// baseline (speedup 1.0000x reference)
#include <cuda_runtime.h>
#include <cstdint>
#include <math.h>

// Problem constants
#define Bc   2
#define Sc   2048
#define Ec   1024
#define Hc   16
#define Dc   64
#define NTOK (Bc*Sc)          // 4096
#define KP2  (Ec/2)           // 512 pairs per row
// attention scale folded into Q at GEMM epilogue, in log2 domain:
// 1/sqrt(64) * log2(e)
#define QSCALE 0.1803368801111244f

// ---------------------------------------------------------------------------
// Scratch (static __device__ — no allocation allowed)
// ---------------------------------------------------------------------------
__device__ uint32_t g_xh [NTOK*KP2];
__device__ uint32_t g_xl [NTOK*KP2];
__device__ uint32_t g_qh [NTOK*KP2];
__device__ uint32_t g_ql [NTOK*KP2];
__device__ uint32_t g_kh [NTOK*KP2];
__device__ uint32_t g_kl [NTOK*KP2];
__device__ uint32_t g_vh [NTOK*KP2];
__device__ uint32_t g_vl [NTOK*KP2];
__device__ uint32_t g_ch [NTOK*KP2];
__device__ uint32_t g_cl [NTOK*KP2];
__device__ uint32_t g_wqh[Ec*KP2];
__device__ uint32_t g_wql[Ec*KP2];
__device__ uint32_t g_wkh[Ec*KP2];
__device__ uint32_t g_wkl[Ec*KP2];
__device__ uint32_t g_wvh[Ec*KP2];
__device__ uint32_t g_wvl[Ec*KP2];
__device__ uint32_t g_woh[Ec*KP2];
__device__ uint32_t g_wol[Ec*KP2];

// ---------------------------------------------------------------------------
// helpers
// ---------------------------------------------------------------------------
__device__ __forceinline__ void split_pack(float v0, float v1, uint32_t& h, uint32_t& l) {
    const uint32_t u0 = __float_as_uint(v0);
    const uint32_t u1 = __float_as_uint(v1);
    uint32_t hp;
    asm("prmt.b32 %0, %1, %2, 0x7632;" : "=r"(hp) : "r"(u0), "r"(u1));
    const float l0 = v0 - __uint_as_float(u0 & 0xFFFF0000u);
    const float l1 = v1 - __uint_as_float(u1 & 0xFFFF0000u);
    uint32_t lp;
    asm("cvt.rn.bf16x2.f32 %0, %1, %2;" : "=r"(lp) : "f"(l1), "f"(l0));
    h = hp; l = lp;
}

__device__ __forceinline__ float ex2(float x) {
    float y;
    asm("ex2.approx.f32 %0, %1;" : "=f"(y) : "f"(x));
    return y;
}

__device__ __forceinline__ void mma_bf16(float* c, const uint32_t* a, const uint32_t* b) {
    asm volatile(
        "mma.sync.aligned.m16n8k16.row.col.f32.bf16.bf16.f32 "
        "{%0,%1,%2,%3}, {%4,%5,%6,%7}, {%8,%9}, {%0,%1,%2,%3};"
        : "+f"(c[0]), "+f"(c[1]), "+f"(c[2]), "+f"(c[3])
        : "r"(a[0]), "r"(a[1]), "r"(a[2]), "r"(a[3]), "r"(b[0]), "r"(b[1]));
}

#define LDM4(r, addr) \
    asm volatile("ldmatrix.sync.aligned.m8n8.x4.shared.b16 {%0,%1,%2,%3}, [%4];" \
        : "=r"((r)[0]), "=r"((r)[1]), "=r"((r)[2]), "=r"((r)[3]) : "r"(addr))
#define LDM4T(r, addr) \
    asm volatile("ldmatrix.sync.aligned.m8n8.x4.trans.shared.b16 {%0,%1,%2,%3}, [%4];" \
        : "=r"((r)[0]), "=r"((r)[1]), "=r"((r)[2]), "=r"((r)[3]) : "r"(addr))
#define CPA16(dst, src) \
    asm volatile("cp.async.ca.shared.global [%0], [%1], 16;" :: "r"(dst), "l"(src))
#define CPA_COMMIT() asm volatile("cp.async.commit_group;" ::: "memory")

__device__ __forceinline__ uint32_t smem_u32(const void* p) {
    uint32_t a;
    asm("{ .reg .u64 t; cvta.to.shared.u64 t, %1; cvt.u32.u64 %0, t; }"
        : "=r"(a) : "l"(p));
    return a;
}

// ---------------------------------------------------------------------------
// split kernel: fp32 -> packed bf16x2 (hi, lo) pair arrays (x + weights only)
// ---------------------------------------------------------------------------
__global__ void __launch_bounds__(256) split_pairs(const float4* __restrict__ x,
                                                   uint2* __restrict__ hp,
                                                   uint2* __restrict__ lp, int n4) {
    const int i = blockIdx.x * 256 + threadIdx.x;
    if (i >= n4) return;
    float4 v = x[i];
    uint32_t h0, l0, h1, l1;
    split_pack(v.x, v.y, h0, l0);
    split_pack(v.z, v.w, h1, l1);
    hp[i] = make_uint2(h0, h1);
    lp[i] = make_uint2(l0, l1);
}

// ---------------------------------------------------------------------------
// 3xBF16 GEMM core: cp.async double-buffered + ldmatrix (R9-proven).
// PAIR outputs scaled by oscale before the split.
// ---------------------------------------------------------------------------
#define PRS  20
#define NPAN 32
#define ARRU (128*PRS)
#define ARRB (ARRU*4)
#define BUFU (4*ARRU)
#define BUFB (BUFU*4)
#define GEMM_SMEM (2*BUFB)     // 81920 B

template<bool PAIR>
__device__ __forceinline__ void gemm_core(const uint32_t* __restrict__ Ahg,
                                          const uint32_t* __restrict__ Alg,
                                          const uint32_t* __restrict__ Bhg,
                                          const uint32_t* __restrict__ Blg,
                                          uint32_t* __restrict__ Oh,
                                          uint32_t* __restrict__ Ol,
                                          float* __restrict__ Cf,
                                          float oscale) {
    extern __shared__ uint32_t smu[];
    const uint32_t sb = smem_u32(smu);

    const int tid  = threadIdx.x;
    const int wid  = tid >> 5;
    const int lane = tid & 31;
    const int wm   = (wid & 1) * 64;
    const int wn   = (wid >> 1) * 32;
    const int m0   = blockIdx.y * 128;
    const int n0   = blockIdx.x * 128;
    const int lq   = lane >> 2;
    const int lr   = lane & 3;

    const uint32_t* gb[4] = { Ahg + (size_t)m0 * KP2, Alg + (size_t)m0 * KP2,
                              Bhg + (size_t)n0 * KP2, Blg + (size_t)n0 * KP2 };

    const uint32_t aPat = (uint32_t)((wm + (lane & 15)) * PRS + (lane >> 4) * 4) * 4;
    const uint32_t bPat = 2 * ARRB +
        (uint32_t)((wn + (lane & 7) + ((lane >> 4) & 1) * 8) * PRS + ((lane >> 3) & 1) * 4) * 4;

    float acc[4][4][4];
    #pragma unroll
    for (int i = 0; i < 4; i++)
        #pragma unroll
        for (int j = 0; j < 4; j++)
            #pragma unroll
            for (int e = 0; e < 4; e++) acc[i][j][e] = 0.f;

    #define STAGE(p, buf) do {                                                  \
        const int _pb = (p) * 16;                                               \
        _Pragma("unroll")                                                       \
        for (int arr = 0; arr < 4; arr++) {                                     \
            _Pragma("unroll")                                                   \
            for (int j = 0; j < 2; j++) {                                       \
                const int i   = tid + j * 256;                                  \
                const int row = i >> 2;                                         \
                const int c   = (i & 3) * 4;                                    \
                const uint32_t* src = gb[arr] + (size_t)row * KP2 + _pb + c;    \
                const uint32_t dst = sb +                                       \
                    (uint32_t)((buf) * BUFU + arr * ARRU + row * PRS + c) * 4;  \
                CPA16(dst, src);                                                \
            }                                                                   \
        }                                                                       \
        CPA_COMMIT();                                                           \
    } while (0)

    STAGE(0, 0);

    for (int p = 0; p < NPAN; p++) {
        if (p + 1 < NPAN) {
            STAGE(p + 1, (p + 1) & 1);
            asm volatile("cp.async.wait_group 1;" ::: "memory");
        } else {
            asm volatile("cp.async.wait_group 0;" ::: "memory");
        }
        __syncthreads();

        const uint32_t bufB = (uint32_t)(p & 1) * BUFB;

        #pragma unroll
        for (int s2 = 0; s2 < 2; s2++) {
            const uint32_t pbB = (uint32_t)s2 * 32;
            uint32_t ah[4][4], al[4][4];
            const uint32_t aa = sb + bufB + aPat + pbB;
            #pragma unroll
            for (int mt = 0; mt < 4; mt++) {
                LDM4(ah[mt], aa + (uint32_t)(mt * 16 * PRS) * 4);
                LDM4(al[mt], aa + (uint32_t)(mt * 16 * PRS) * 4 + ARRB);
            }
            const uint32_t ba = sb + bufB + bPat + pbB;
            #pragma unroll
            for (int ntp = 0; ntp < 2; ntp++) {
                uint32_t bh[4], bl[4];
                LDM4(bh, ba + (uint32_t)(ntp * 16 * PRS) * 4);
                LDM4(bl, ba + (uint32_t)(ntp * 16 * PRS) * 4 + ARRB);
                #pragma unroll
                for (int mt = 0; mt < 4; mt++) {
                    mma_bf16(acc[mt][2*ntp],   ah[mt], bh);
                    mma_bf16(acc[mt][2*ntp],   ah[mt], bl);
                    mma_bf16(acc[mt][2*ntp],   al[mt], bh);
                    mma_bf16(acc[mt][2*ntp+1], ah[mt], bh + 2);
                    mma_bf16(acc[mt][2*ntp+1], ah[mt], bl + 2);
                    mma_bf16(acc[mt][2*ntp+1], al[mt], bh + 2);
                }
            }
        }
        __syncthreads();
    }

    #pragma unroll
    for (int mt = 0; mt < 4; mt++) {
        const int r0 = m0 + wm + mt * 16 + lq;
        #pragma unroll
        for (int nt = 0; nt < 4; nt++) {
            if (PAIR) {
                const int pidx = ((n0 + wn + nt * 8) >> 1) + lr;
                uint32_t h, l;
                split_pack(acc[mt][nt][0] * oscale, acc[mt][nt][1] * oscale, h, l);
                Oh[(size_t)r0 * KP2 + pidx] = h;
                Ol[(size_t)r0 * KP2 + pidx] = l;
                split_pack(acc[mt][nt][2] * oscale, acc[mt][nt][3] * oscale, h, l);
                Oh[(size_t)(r0 + 8) * KP2 + pidx] = h;
                Ol[(size_t)(r0 + 8) * KP2 + pidx] = l;
            } else {
                const int cc = n0 + wn + nt * 8 + lr * 2;
                *(float2*)&Cf[(size_t)r0 * Ec + cc]       = make_float2(acc[mt][nt][0], acc[mt][nt][1]);
                *(float2*)&Cf[(size_t)(r0 + 8) * Ec + cc] = make_float2(acc[mt][nt][2], acc[mt][nt][3]);
            }
        }
    }
}

__global__ void __launch_bounds__(256, 2) gemm_qkv(
    const uint32_t* __restrict__ xh,  const uint32_t* __restrict__ xl,
    const uint32_t* __restrict__ wqh, const uint32_t* __restrict__ wql,
    const uint32_t* __restrict__ wkh, const uint32_t* __restrict__ wkl,
    const uint32_t* __restrict__ wvh, const uint32_t* __restrict__ wvl,
    uint32_t* __restrict__ qh, uint32_t* __restrict__ ql,
    uint32_t* __restrict__ kh, uint32_t* __restrict__ kl,
    uint32_t* __restrict__ vh, uint32_t* __restrict__ vl) {
    const uint32_t *bh, *bl;
    uint32_t *oh, *ol;
    float sc;
    if (blockIdx.z == 0)      { bh = wqh; bl = wql; oh = qh; ol = ql; sc = QSCALE; }
    else if (blockIdx.z == 1) { bh = wkh; bl = wkl; oh = kh; ol = kl; sc = 1.0f; }
    else                      { bh = wvh; bl = wvl; oh = vh; ol = vl; sc = 1.0f; }
    gemm_core<true>(xh, xl, bh, bl, oh, ol, nullptr, sc);
}

__global__ void __launch_bounds__(256, 2) gemm_wo(
    const uint32_t* __restrict__ ch, const uint32_t* __restrict__ cl,
    const uint32_t* __restrict__ woh, const uint32_t* __restrict__ wol,
    float* __restrict__ out) {
    gemm_core<false>(ch, cl, woh, wol, nullptr, nullptr, out, 1.0f);
}

// ---------------------------------------------------------------------------
// Flash attention, causal, 3xBF16. Br=128, 8 warps (warp = 16 rows x 64 keys),
// KV double-buffered via cp.async groups. 110592 B smem -> 2 CTAs/SM (16 w/SM).
// Scale pre-folded into Q (log2 domain); softmax uses ex2.
// ---------------------------------------------------------------------------
#define PST   36
#define QAB   ((uint32_t)(128*PST)*4)    // bytes per Q array (18432)
#define KVOFF (2*QAB)                    // 36864
#define KVB   ((uint32_t)(64*PST)*4)     // 9216
#define BUFOFF (4*KVB)                   // 36864
#define FA_SMEM (KVOFF + 2*BUFOFF)       // 110592 B

__global__ void __launch_bounds__(256, 2) flash_attn_mma(
    const uint32_t* __restrict__ Qh, const uint32_t* __restrict__ Ql,
    const uint32_t* __restrict__ Kh, const uint32_t* __restrict__ Kl,
    const uint32_t* __restrict__ Vh, const uint32_t* __restrict__ Vl,
    uint32_t* __restrict__ Ch, uint32_t* __restrict__ Cl) {
    extern __shared__ uint32_t smu[];
    const uint32_t sbq = smem_u32(smu);

    const int tid  = threadIdx.x;
    const int wid  = tid >> 5;          // 0..7
    const int lane = tid & 31;
    const int lq   = lane >> 2;
    const int lr   = lane & 3;
    const int wrow = wid * 16;

    const int qt = gridDim.x - 1 - blockIdx.x;   // long CTAs first
    const int h  = blockIdx.y;
    const int b  = blockIdx.z;
    const int hb = h * 32;
    const size_t rb = (size_t)b * Sc;
    const int rowbase = qt * 128;
    const int jtmax = 2 * qt + 1;

    // fragment lane patterns (byte offsets)
    const uint32_t aPat = sbq +
        (uint32_t)((wrow + (lane & 15)) * PST + (lane >> 4) * 4) * 4;
    const uint32_t kPat =
        (uint32_t)(((lane & 7) + ((lane >> 4) & 1) * 8) * PST + ((lane >> 3) & 1) * 4) * 4;
    const uint32_t vPat = 2 * KVB +
        (uint32_t)(((lane & 7) + ((lane >> 3) & 1) * 8) * PST + ((lane >> 4) & 1) * 4) * 4;

    // stage Q (128 rows x 2 arrays) + KV tile 0, one cp.async group
    #pragma unroll
    for (int it = 0; it < 4; it++) {
        const int i   = tid + it * 256;          // 1024 chunks per array
        const int row = i >> 3;
        const int c   = (i & 7) * 4;
        const size_t src = (rb + rowbase + row) * KP2 + hb + c;
        const uint32_t dst = sbq + (uint32_t)(row * PST + c) * 4;
        CPA16(dst, Qh + src);
        CPA16(dst + QAB, Ql + src);
    }
    #pragma unroll
    for (int it = 0; it < 2; it++) {
        const int i   = tid + it * 256;          // 512 chunks per array
        const int row = i >> 3;
        const int c   = (i & 7) * 4;
        const size_t src = (rb + row) * KP2 + hb + c;
        const uint32_t dst = sbq + KVOFF + (uint32_t)(row * PST + c) * 4;
        CPA16(dst,           Kh + src);
        CPA16(dst + KVB,     Kl + src);
        CPA16(dst + 2 * KVB, Vh + src);
        CPA16(dst + 3 * KVB, Vl + src);
    }
    CPA_COMMIT();

    float o[8][4];
    #pragma unroll
    for (int nt = 0; nt < 8; nt++)
        #pragma unroll
        for (int e = 0; e < 4; e++) o[nt][e] = 0.f;
    float mr0 = -1e30f, mr1 = -1e30f, lr0 = 0.f, lr1 = 0.f;

    const unsigned FM = 0xffffffffu;

    for (int jt = 0; jt <= jtmax; jt++) {
        __syncthreads();   // all warps done reading buf (jt+1)&1 (from jt-1)
        if (jt < jtmax) {
            const uint32_t kvb = sbq + KVOFF + (uint32_t)((jt + 1) & 1) * BUFOFF;
            #pragma unroll
            for (int it = 0; it < 2; it++) {
                const int i   = tid + it * 256;
                const int row = i >> 3;
                const int c   = (i & 7) * 4;
                const size_t src = (rb + (jt + 1) * 64 + row) * KP2 + hb + c;
                const uint32_t dst = kvb + (uint32_t)(row * PST + c) * 4;
                CPA16(dst,           Kh + src);
                CPA16(dst + KVB,     Kl + src);
                CPA16(dst + 2 * KVB, Vh + src);
                CPA16(dst + 3 * KVB, Vl + src);
            }
            CPA_COMMIT();
            asm volatile("cp.async.wait_group 1;" ::: "memory");
        } else {
            asm volatile("cp.async.wait_group 0;" ::: "memory");
        }
        __syncthreads();

        if (jt * 64 > rowbase + wrow + 15) continue;   // warp causal skip

        const uint32_t kvb = sbq + KVOFF + (uint32_t)(jt & 1) * BUFOFF;
        const uint32_t kBase = kvb + kPat;
        const uint32_t vBase = kvb + vPat;

        // S = Q @ K^T  (Q pre-scaled into log2 domain)
        float s[8][4];
        #pragma unroll
        for (int nt = 0; nt < 8; nt++)
            #pragma unroll
            for (int e = 0; e < 4; e++) s[nt][e] = 0.f;

        #pragma unroll
        for (int ks = 0; ks < 4; ks++) {
            const uint32_t pbB = (uint32_t)ks * 32;
            uint32_t ah[4], al[4];
            LDM4(ah, aPat + pbB);
            LDM4(al, aPat + QAB + pbB);
            #pragma unroll
            for (int ntp = 0; ntp < 4; ntp++) {
                const uint32_t ka = kBase + (uint32_t)(ntp * 16 * PST) * 4 + pbB;
                uint32_t bh[4], bl[4];
                LDM4(bh, ka);
                LDM4(bl, ka + KVB);
                mma_bf16(s[2*ntp],   ah, bh);
                mma_bf16(s[2*ntp],   ah, bl);
                mma_bf16(s[2*ntp],   al, bh);
                mma_bf16(s[2*ntp+1], ah, bh + 2);
                mma_bf16(s[2*ntp+1], ah, bl + 2);
                mma_bf16(s[2*ntp+1], al, bh + 2);
            }
        }

        // causal mask (scale already folded into Q)
        if (jt * 64 + 63 > rowbase + wrow) {
            const int row0 = rowbase + wrow + lq;
            const int row1 = row0 + 8;
            #pragma unroll
            for (int nt = 0; nt < 8; nt++) {
                const int c0 = jt * 64 + nt * 8 + lr * 2;
                if (c0     > row0) s[nt][0] = -1e30f;
                if (c0 + 1 > row0) s[nt][1] = -1e30f;
                if (c0     > row1) s[nt][2] = -1e30f;
                if (c0 + 1 > row1) s[nt][3] = -1e30f;
            }
        }

        // online softmax (base-2)
        float mt0 = -1e30f, mt1 = -1e30f;
        #pragma unroll
        for (int nt = 0; nt < 8; nt++) {
            mt0 = fmaxf(mt0, fmaxf(s[nt][0], s[nt][1]));
            mt1 = fmaxf(mt1, fmaxf(s[nt][2], s[nt][3]));
        }
        mt0 = fmaxf(mt0, __shfl_xor_sync(FM, mt0, 1));
        mt0 = fmaxf(mt0, __shfl_xor_sync(FM, mt0, 2));
        mt1 = fmaxf(mt1, __shfl_xor_sync(FM, mt1, 1));
        mt1 = fmaxf(mt1, __shfl_xor_sync(FM, mt1, 2));
        const float mn0 = fmaxf(mr0, mt0);
        const float mn1 = fmaxf(mr1, mt1);
        const float a0 = ex2(mr0 - mn0);
        const float a1 = ex2(mr1 - mn1);
        float rs0 = 0.f, rs1 = 0.f;
        #pragma unroll
        for (int nt = 0; nt < 8; nt++) {
            s[nt][0] = ex2(s[nt][0] - mn0); rs0 += s[nt][0];
            s[nt][1] = ex2(s[nt][1] - mn0); rs0 += s[nt][1];
            s[nt][2] = ex2(s[nt][2] - mn1); rs1 += s[nt][2];
            s[nt][3] = ex2(s[nt][3] - mn1); rs1 += s[nt][3];
        }
        rs0 += __shfl_xor_sync(FM, rs0, 1);
        rs0 += __shfl_xor_sync(FM, rs0, 2);
        rs1 += __shfl_xor_sync(FM, rs1, 1);
        rs1 += __shfl_xor_sync(FM, rs1, 2);
        lr0 = lr0 * a0 + rs0; mr0 = mn0;
        lr1 = lr1 * a1 + rs1; mr1 = mn1;
        #pragma unroll
        for (int nt = 0; nt < 8; nt++) {
            o[nt][0] *= a0; o[nt][1] *= a0;
            o[nt][2] *= a1; o[nt][3] *= a1;
        }

        // O += P @ V (P from S registers, V via ldmatrix.trans)
        #pragma unroll
        for (int ks = 0; ks < 4; ks++) {
            uint32_t ph[4], pl[4];
            split_pack(s[2*ks][0],   s[2*ks][1],   ph[0], pl[0]);
            split_pack(s[2*ks][2],   s[2*ks][3],   ph[1], pl[1]);
            split_pack(s[2*ks+1][0], s[2*ks+1][1], ph[2], pl[2]);
            split_pack(s[2*ks+1][2], s[2*ks+1][3], ph[3], pl[3]);
            const uint32_t kOfs = (uint32_t)(ks * 16 * PST) * 4;
            #pragma unroll
            for (int ntp = 0; ntp < 4; ntp++) {
                const uint32_t va = vBase + kOfs + (uint32_t)(ntp * 8) * 4;
                uint32_t vh[4], vl[4];
                LDM4T(vh, va);
                LDM4T(vl, va + KVB);
                mma_bf16(o[2*ntp],   ph, vh);
                mma_bf16(o[2*ntp],   ph, vl);
                mma_bf16(o[2*ntp],   pl, vh);
                mma_bf16(o[2*ntp+1], ph, vh + 2);
                mma_bf16(o[2*ntp+1], ph, vl + 2);
                mma_bf16(o[2*ntp+1], pl, vh + 2);
            }
        }
    }

    // epilogue: normalize, write split pairs for the WO GEMM
    const float inv0 = 1.0f / lr0;
    const float inv1 = 1.0f / lr1;
    const size_t ro0 = (rb + rowbase + wrow + lq) * KP2 + hb;
    const size_t ro1 = ro0 + 8 * (size_t)KP2;
    #pragma unroll
    for (int nt = 0; nt < 8; nt++) {
        const int pidx = nt * 4 + lr;
        uint32_t hp, lp;
        split_pack(o[nt][0] * inv0, o[nt][1] * inv0, hp, lp);
        Ch[ro0 + pidx] = hp; Cl[ro0 + pidx] = lp;
        split_pack(o[nt][2] * inv1, o[nt][3] * inv1, hp, lp);
        Ch[ro1 + pidx] = hp; Cl[ro1 + pidx] = lp;
    }
}

// ---------------------------------------------------------------------------
extern "C" void kernel_launch(void* const* d_in, const int* in_sizes, int n_in,
                              void* d_out, int out_size) {
    (void)in_sizes; (void)n_in; (void)out_size;
    const float* x  = (const float*)d_in[0];
    const float* wq = (const float*)d_in[1];
    const float* wk = (const float*)d_in[2];
    const float* wv = (const float*)d_in[3];
    const float* wo = (const float*)d_in[4];
    float* out = (float*)d_out;

    uint32_t *xh, *xl, *qh, *ql, *kh, *kl, *vh, *vl, *ch, *cl;
    uint32_t *wqh, *wql, *wkh, *wkl, *wvh, *wvl, *woh, *wol;
    cudaGetSymbolAddress((void**)&xh,  g_xh);
    cudaGetSymbolAddress((void**)&xl,  g_xl);
    cudaGetSymbolAddress((void**)&qh,  g_qh);
    cudaGetSymbolAddress((void**)&ql,  g_ql);
    cudaGetSymbolAddress((void**)&kh,  g_kh);
    cudaGetSymbolAddress((void**)&kl,  g_kl);
    cudaGetSymbolAddress((void**)&vh,  g_vh);
    cudaGetSymbolAddress((void**)&vl,  g_vl);
    cudaGetSymbolAddress((void**)&ch,  g_ch);
    cudaGetSymbolAddress((void**)&cl,  g_cl);
    cudaGetSymbolAddress((void**)&wqh, g_wqh);
    cudaGetSymbolAddress((void**)&wql, g_wql);
    cudaGetSymbolAddress((void**)&wkh, g_wkh);
    cudaGetSymbolAddress((void**)&wkl, g_wkl);
    cudaGetSymbolAddress((void**)&wvh, g_wvh);
    cudaGetSymbolAddress((void**)&wvl, g_wvl);
    cudaGetSymbolAddress((void**)&woh, g_woh);
    cudaGetSymbolAddress((void**)&wol, g_wol);

    const int nx4 = NTOK * Ec / 4;
    const int nw4 = Ec * Ec / 4;
    split_pairs<<<nx4 / 256, 256>>>((const float4*)x,  (uint2*)xh,  (uint2*)xl,  nx4);
    split_pairs<<<nw4 / 256, 256>>>((const float4*)wq, (uint2*)wqh, (uint2*)wql, nw4);
    split_pairs<<<nw4 / 256, 256>>>((const float4*)wk, (uint2*)wkh, (uint2*)wkl, nw4);
    split_pairs<<<nw4 / 256, 256>>>((const float4*)wv, (uint2*)wvh, (uint2*)wvl, nw4);
    split_pairs<<<nw4 / 256, 256>>>((const float4*)wo, (uint2*)woh, (uint2*)wol, nw4);

    cudaFuncSetAttribute(gemm_qkv, cudaFuncAttributeMaxDynamicSharedMemorySize, GEMM_SMEM);
    cudaFuncSetAttribute(gemm_wo,  cudaFuncAttributeMaxDynamicSharedMemorySize, GEMM_SMEM);

    gemm_qkv<<<dim3(Ec / 128, NTOK / 128, 3), 256, GEMM_SMEM>>>(
        xh, xl, wqh, wql, wkh, wkl, wvh, wvl, qh, ql, kh, kl, vh, vl);

    cudaFuncSetAttribute(flash_attn_mma, cudaFuncAttributeMaxDynamicSharedMemorySize, FA_SMEM);
    flash_attn_mma<<<dim3(Sc / 128, Hc, Bc), 256, FA_SMEM>>>(qh, ql, kh, kl, vh, vl, ch, cl);

    gemm_wo<<<dim3(Ec / 128, NTOK / 128), 256, GEMM_SMEM>>>(ch, cl, woh, wol, out);
}

// round 12
// speedup vs baseline: 1.0216x; 1.0216x over previous
#include <cuda_runtime.h>
#include <cstdint>
#include <math.h>

// Problem constants
#define Bc   2
#define Sc   2048
#define Ec   1024
#define Hc   16
#define Dc   64
#define NTOK (Bc*Sc)          // 4096
#define KP2  (Ec/2)           // 512 pairs per row
// attention scale folded into Q at GEMM epilogue, log2 domain: (1/8)*log2(e)
#define QSCALE 0.1803368801111244f

// ---------------------------------------------------------------------------
// Scratch (static __device__ — no allocation allowed)
// ---------------------------------------------------------------------------
__device__ uint32_t g_xh [NTOK*KP2];
__device__ uint32_t g_xl [NTOK*KP2];
__device__ uint32_t g_qh [NTOK*KP2];
__device__ uint32_t g_ql [NTOK*KP2];
__device__ uint32_t g_kh [NTOK*KP2];
__device__ uint32_t g_kl [NTOK*KP2];
__device__ uint32_t g_vh [NTOK*KP2];
__device__ uint32_t g_vl [NTOK*KP2];
__device__ uint32_t g_ch [NTOK*KP2];
__device__ uint32_t g_cl [NTOK*KP2];
__device__ uint32_t g_wqh[Ec*KP2];
__device__ uint32_t g_wql[Ec*KP2];
__device__ uint32_t g_wkh[Ec*KP2];
__device__ uint32_t g_wkl[Ec*KP2];
__device__ uint32_t g_wvh[Ec*KP2];
__device__ uint32_t g_wvl[Ec*KP2];
__device__ uint32_t g_woh[Ec*KP2];
__device__ uint32_t g_wol[Ec*KP2];

// ---------------------------------------------------------------------------
// helpers
// ---------------------------------------------------------------------------
__device__ __forceinline__ void split_pack(float v0, float v1, uint32_t& h, uint32_t& l) {
    const uint32_t u0 = __float_as_uint(v0);
    const uint32_t u1 = __float_as_uint(v1);
    uint32_t hp;
    asm("prmt.b32 %0, %1, %2, 0x7632;" : "=r"(hp) : "r"(u0), "r"(u1));
    const float l0 = v0 - __uint_as_float(u0 & 0xFFFF0000u);
    const float l1 = v1 - __uint_as_float(u1 & 0xFFFF0000u);
    uint32_t lp;
    asm("cvt.rn.bf16x2.f32 %0, %1, %2;" : "=r"(lp) : "f"(l1), "f"(l0));
    h = hp; l = lp;
}

__device__ __forceinline__ float ex2(float x) {
    float y;
    asm("ex2.approx.f32 %0, %1;" : "=f"(y) : "f"(x));
    return y;
}

__device__ __forceinline__ void mma_bf16(float* c, const uint32_t* a, const uint32_t* b) {
    asm volatile(
        "mma.sync.aligned.m16n8k16.row.col.f32.bf16.bf16.f32 "
        "{%0,%1,%2,%3}, {%4,%5,%6,%7}, {%8,%9}, {%0,%1,%2,%3};"
        : "+f"(c[0]), "+f"(c[1]), "+f"(c[2]), "+f"(c[3])
        : "r"(a[0]), "r"(a[1]), "r"(a[2]), "r"(a[3]), "r"(b[0]), "r"(b[1]));
}

#define LDM4(r, addr) \
    asm volatile("ldmatrix.sync.aligned.m8n8.x4.shared.b16 {%0,%1,%2,%3}, [%4];" \
        : "=r"((r)[0]), "=r"((r)[1]), "=r"((r)[2]), "=r"((r)[3]) : "r"(addr))
#define LDM4T(r, addr) \
    asm volatile("ldmatrix.sync.aligned.m8n8.x4.trans.shared.b16 {%0,%1,%2,%3}, [%4];" \
        : "=r"((r)[0]), "=r"((r)[1]), "=r"((r)[2]), "=r"((r)[3]) : "r"(addr))
#define CPA16(dst, src) \
    asm volatile("cp.async.ca.shared.global [%0], [%1], 16;" :: "r"(dst), "l"(src))
#define CPA_COMMIT() asm volatile("cp.async.commit_group;" ::: "memory")

__device__ __forceinline__ uint32_t smem_u32(const void* p) {
    uint32_t a;
    asm("{ .reg .u64 t; cvta.to.shared.u64 t, %1; cvt.u32.u64 %0, t; }"
        : "=r"(a) : "l"(p));
    return a;
}

// ---------------------------------------------------------------------------
// split kernel: fp32 -> packed bf16x2 (hi, lo) pair arrays (x + weights only)
// ---------------------------------------------------------------------------
__global__ void __launch_bounds__(256) split_pairs(const float4* __restrict__ x,
                                                   uint2* __restrict__ hp,
                                                   uint2* __restrict__ lp, int n4) {
    const int i = blockIdx.x * 256 + threadIdx.x;
    if (i >= n4) return;
    float4 v = x[i];
    uint32_t h0, l0, h1, l1;
    split_pack(v.x, v.y, h0, l0);
    split_pack(v.z, v.w, h1, l1);
    hp[i] = make_uint2(h0, h1);
    lp[i] = make_uint2(l0, l1);
}

// ---------------------------------------------------------------------------
// 3xBF16 GEMM core: cp.async double-buffered + ldmatrix (R9-proven).
// PAIR outputs scaled by oscale before the split.
// ---------------------------------------------------------------------------
#define PRS  20
#define NPAN 32
#define ARRU (128*PRS)
#define ARRB (ARRU*4)
#define BUFU (4*ARRU)
#define BUFB (BUFU*4)
#define GEMM_SMEM (2*BUFB)     // 81920 B

template<bool PAIR>
__device__ __forceinline__ void gemm_core(const uint32_t* __restrict__ Ahg,
                                          const uint32_t* __restrict__ Alg,
                                          const uint32_t* __restrict__ Bhg,
                                          const uint32_t* __restrict__ Blg,
                                          uint32_t* __restrict__ Oh,
                                          uint32_t* __restrict__ Ol,
                                          float* __restrict__ Cf,
                                          float oscale) {
    extern __shared__ uint32_t smu[];
    const uint32_t sb = smem_u32(smu);

    const int tid  = threadIdx.x;
    const int wid  = tid >> 5;
    const int lane = tid & 31;
    const int wm   = (wid & 1) * 64;
    const int wn   = (wid >> 1) * 32;
    const int m0   = blockIdx.y * 128;
    const int n0   = blockIdx.x * 128;
    const int lq   = lane >> 2;
    const int lr   = lane & 3;

    const uint32_t* gb[4] = { Ahg + (size_t)m0 * KP2, Alg + (size_t)m0 * KP2,
                              Bhg + (size_t)n0 * KP2, Blg + (size_t)n0 * KP2 };

    const uint32_t aPat = (uint32_t)((wm + (lane & 15)) * PRS + (lane >> 4) * 4) * 4;
    const uint32_t bPat = 2 * ARRB +
        (uint32_t)((wn + (lane & 7) + ((lane >> 4) & 1) * 8) * PRS + ((lane >> 3) & 1) * 4) * 4;

    float acc[4][4][4];
    #pragma unroll
    for (int i = 0; i < 4; i++)
        #pragma unroll
        for (int j = 0; j < 4; j++)
            #pragma unroll
            for (int e = 0; e < 4; e++) acc[i][j][e] = 0.f;

    #define STAGE(p, buf) do {                                                  \
        const int _pb = (p) * 16;                                               \
        _Pragma("unroll")                                                       \
        for (int arr = 0; arr < 4; arr++) {                                     \
            _Pragma("unroll")                                                   \
            for (int j = 0; j < 2; j++) {                                       \
                const int i   = tid + j * 256;                                  \
                const int row = i >> 2;                                         \
                const int c   = (i & 3) * 4;                                    \
                const uint32_t* src = gb[arr] + (size_t)row * KP2 + _pb + c;    \
                const uint32_t dst = sb +                                       \
                    (uint32_t)((buf) * BUFU + arr * ARRU + row * PRS + c) * 4;  \
                CPA16(dst, src);                                                \
            }                                                                   \
        }                                                                       \
        CPA_COMMIT();                                                           \
    } while (0)

    STAGE(0, 0);

    for (int p = 0; p < NPAN; p++) {
        if (p + 1 < NPAN) {
            STAGE(p + 1, (p + 1) & 1);
            asm volatile("cp.async.wait_group 1;" ::: "memory");
        } else {
            asm volatile("cp.async.wait_group 0;" ::: "memory");
        }
        __syncthreads();

        const uint32_t bufB = (uint32_t)(p & 1) * BUFB;

        #pragma unroll
        for (int s2 = 0; s2 < 2; s2++) {
            const uint32_t pbB = (uint32_t)s2 * 32;
            uint32_t ah[4][4], al[4][4];
            const uint32_t aa = sb + bufB + aPat + pbB;
            #pragma unroll
            for (int mt = 0; mt < 4; mt++) {
                LDM4(ah[mt], aa + (uint32_t)(mt * 16 * PRS) * 4);
                LDM4(al[mt], aa + (uint32_t)(mt * 16 * PRS) * 4 + ARRB);
            }
            const uint32_t ba = sb + bufB + bPat + pbB;
            #pragma unroll
            for (int ntp = 0; ntp < 2; ntp++) {
                uint32_t bh[4], bl[4];
                LDM4(bh, ba + (uint32_t)(ntp * 16 * PRS) * 4);
                LDM4(bl, ba + (uint32_t)(ntp * 16 * PRS) * 4 + ARRB);
                #pragma unroll
                for (int mt = 0; mt < 4; mt++) {
                    mma_bf16(acc[mt][2*ntp],   ah[mt], bh);
                    mma_bf16(acc[mt][2*ntp],   ah[mt], bl);
                    mma_bf16(acc[mt][2*ntp],   al[mt], bh);
                    mma_bf16(acc[mt][2*ntp+1], ah[mt], bh + 2);
                    mma_bf16(acc[mt][2*ntp+1], ah[mt], bl + 2);
                    mma_bf16(acc[mt][2*ntp+1], al[mt], bh + 2);
                }
            }
        }
        __syncthreads();
    }

    #pragma unroll
    for (int mt = 0; mt < 4; mt++) {
        const int r0 = m0 + wm + mt * 16 + lq;
        #pragma unroll
        for (int nt = 0; nt < 4; nt++) {
            if (PAIR) {
                const int pidx = ((n0 + wn + nt * 8) >> 1) + lr;
                uint32_t h, l;
                split_pack(acc[mt][nt][0] * oscale, acc[mt][nt][1] * oscale, h, l);
                Oh[(size_t)r0 * KP2 + pidx] = h;
                Ol[(size_t)r0 * KP2 + pidx] = l;
                split_pack(acc[mt][nt][2] * oscale, acc[mt][nt][3] * oscale, h, l);
                Oh[(size_t)(r0 + 8) * KP2 + pidx] = h;
                Ol[(size_t)(r0 + 8) * KP2 + pidx] = l;
            } else {
                const int cc = n0 + wn + nt * 8 + lr * 2;
                *(float2*)&Cf[(size_t)r0 * Ec + cc]       = make_float2(acc[mt][nt][0], acc[mt][nt][1]);
                *(float2*)&Cf[(size_t)(r0 + 8) * Ec + cc] = make_float2(acc[mt][nt][2], acc[mt][nt][3]);
            }
        }
    }
}

__global__ void __launch_bounds__(256, 2) gemm_qkv(
    const uint32_t* __restrict__ xh,  const uint32_t* __restrict__ xl,
    const uint32_t* __restrict__ wqh, const uint32_t* __restrict__ wql,
    const uint32_t* __restrict__ wkh, const uint32_t* __restrict__ wkl,
    const uint32_t* __restrict__ wvh, const uint32_t* __restrict__ wvl,
    uint32_t* __restrict__ qh, uint32_t* __restrict__ ql,
    uint32_t* __restrict__ kh, uint32_t* __restrict__ kl,
    uint32_t* __restrict__ vh, uint32_t* __restrict__ vl) {
    const uint32_t *bh, *bl;
    uint32_t *oh, *ol;
    float sc;
    if (blockIdx.z == 0)      { bh = wqh; bl = wql; oh = qh; ol = ql; sc = QSCALE; }
    else if (blockIdx.z == 1) { bh = wkh; bl = wkl; oh = kh; ol = kl; sc = 1.0f; }
    else                      { bh = wvh; bl = wvl; oh = vh; ol = vl; sc = 1.0f; }
    gemm_core<true>(xh, xl, bh, bl, oh, ol, nullptr, sc);
}

__global__ void __launch_bounds__(256, 2) gemm_wo(
    const uint32_t* __restrict__ ch, const uint32_t* __restrict__ cl,
    const uint32_t* __restrict__ woh, const uint32_t* __restrict__ wol,
    float* __restrict__ out) {
    gemm_core<false>(ch, cl, woh, wol, nullptr, nullptr, out, 1.0f);
}

// ---------------------------------------------------------------------------
// Flash attention, causal, 3xBF16 m16n8k16 — R9 geometry (proven):
// Br=64, 128 thr, 4 CTAs/SM, cp.async staging, ldmatrix(+trans for V).
// Scale pre-folded into Q (log2 domain); softmax via ex2.
// ---------------------------------------------------------------------------
#define PST 36
#define QLB ((uint32_t)(64*PST)*4)        // bytes per array
#define FA_SMEM (6 * 64 * PST * 4)        // 55296 B

__global__ void __launch_bounds__(128, 4) flash_attn_mma(
    const uint32_t* __restrict__ Qh, const uint32_t* __restrict__ Ql,
    const uint32_t* __restrict__ Kh, const uint32_t* __restrict__ Kl,
    const uint32_t* __restrict__ Vh, const uint32_t* __restrict__ Vl,
    uint32_t* __restrict__ Ch, uint32_t* __restrict__ Cl) {
    extern __shared__ uint32_t smu[];
    const uint32_t sbq = smem_u32(smu);

    const int tid  = threadIdx.x;
    const int wid  = tid >> 5;
    const int lane = tid & 31;
    const int lq   = lane >> 2;
    const int lr   = lane & 3;
    const int wrow = wid * 16;

    const int qt = gridDim.x - 1 - blockIdx.x;
    const int h  = blockIdx.y;
    const int b  = blockIdx.z;
    const int hb = h * 32;
    const size_t rb = (size_t)b * Sc;

    // fragment lane patterns (byte offsets)
    const uint32_t aPat = sbq +
        (uint32_t)((wrow + (lane & 15)) * PST + (lane >> 4) * 4) * 4;
    const uint32_t kPat = sbq + 2 * QLB +
        (uint32_t)(((lane & 7) + ((lane >> 4) & 1) * 8) * PST + ((lane >> 3) & 1) * 4) * 4;
    const uint32_t vPat = sbq + 4 * QLB +
        (uint32_t)(((lane & 7) + ((lane >> 3) & 1) * 8) * PST + ((lane >> 4) & 1) * 4) * 4;

    // stage Q via cp.async (waited inside first loop iteration)
    #pragma unroll
    for (int it = 0; it < 4; it++) {
        const int i   = tid + it * 128;            // 512 chunks per array
        const int row = i >> 3;
        const int c   = (i & 7) * 4;               // u32 offset
        const size_t src = (rb + qt * 64 + row) * KP2 + hb + c;
        const uint32_t dst = sbq + (uint32_t)(row * PST + c) * 4;
        CPA16(dst, Qh + src);
        CPA16(dst + QLB, Ql + src);
    }
    CPA_COMMIT();

    float o[8][4];
    #pragma unroll
    for (int nt = 0; nt < 8; nt++)
        #pragma unroll
        for (int e = 0; e < 4; e++) o[nt][e] = 0.f;
    float mr0 = -1e30f, mr1 = -1e30f, lr0 = 0.f, lr1 = 0.f;

    const unsigned FM = 0xffffffffu;

    for (int jt = 0; jt <= qt; jt++) {
        __syncthreads();   // previous iteration done reading K/V smem
        #pragma unroll
        for (int it = 0; it < 4; it++) {
            const int i   = tid + it * 128;
            const int row = i >> 3;
            const int c   = (i & 7) * 4;
            const size_t src = (rb + jt * 64 + row) * KP2 + hb + c;
            const uint32_t dst = sbq + (uint32_t)(row * PST + c) * 4;
            CPA16(dst + 2 * QLB, Kh + src);
            CPA16(dst + 3 * QLB, Kl + src);
            CPA16(dst + 4 * QLB, Vh + src);
            CPA16(dst + 5 * QLB, Vl + src);
        }
        CPA_COMMIT();
        asm volatile("cp.async.wait_group 0;" ::: "memory");
        __syncthreads();

        // S = Q @ K^T  (Q pre-scaled into log2 domain)
        float s[8][4];
        #pragma unroll
        for (int nt = 0; nt < 8; nt++)
            #pragma unroll
            for (int e = 0; e < 4; e++) s[nt][e] = 0.f;

        #pragma unroll
        for (int ks = 0; ks < 4; ks++) {
            const uint32_t pbB = (uint32_t)ks * 32;
            uint32_t ah[4], al[4];
            LDM4(ah, aPat + pbB);
            LDM4(al, aPat + QLB + pbB);
            #pragma unroll
            for (int ntp = 0; ntp < 4; ntp++) {
                const uint32_t ka = kPat + (uint32_t)(ntp * 16 * PST) * 4 + pbB;
                uint32_t bh[4], bl[4];
                LDM4(bh, ka);
                LDM4(bl, ka + QLB);
                mma_bf16(s[2*ntp],   ah, bh);
                mma_bf16(s[2*ntp],   ah, bl);
                mma_bf16(s[2*ntp],   al, bh);
                mma_bf16(s[2*ntp+1], ah, bh + 2);
                mma_bf16(s[2*ntp+1], ah, bl + 2);
                mma_bf16(s[2*ntp+1], al, bh + 2);
            }
        }

        // causal mask (scale already folded into Q)
        if (jt == qt) {
            const int row0 = wrow + lq, row1 = wrow + lq + 8;
            #pragma unroll
            for (int nt = 0; nt < 8; nt++) {
                const int c0 = nt * 8 + lr * 2;
                if (c0     > row0) s[nt][0] = -1e30f;
                if (c0 + 1 > row0) s[nt][1] = -1e30f;
                if (c0     > row1) s[nt][2] = -1e30f;
                if (c0 + 1 > row1) s[nt][3] = -1e30f;
            }
        }

        // online softmax (base-2)
        float mt0 = -1e30f, mt1 = -1e30f;
        #pragma unroll
        for (int nt = 0; nt < 8; nt++) {
            mt0 = fmaxf(mt0, fmaxf(s[nt][0], s[nt][1]));
            mt1 = fmaxf(mt1, fmaxf(s[nt][2], s[nt][3]));
        }
        mt0 = fmaxf(mt0, __shfl_xor_sync(FM, mt0, 1));
        mt0 = fmaxf(mt0, __shfl_xor_sync(FM, mt0, 2));
        mt1 = fmaxf(mt1, __shfl_xor_sync(FM, mt1, 1));
        mt1 = fmaxf(mt1, __shfl_xor_sync(FM, mt1, 2));
        const float mn0 = fmaxf(mr0, mt0);
        const float mn1 = fmaxf(mr1, mt1);
        const float a0 = ex2(mr0 - mn0);
        const float a1 = ex2(mr1 - mn1);
        float rs0 = 0.f, rs1 = 0.f;
        #pragma unroll
        for (int nt = 0; nt < 8; nt++) {
            s[nt][0] = ex2(s[nt][0] - mn0); rs0 += s[nt][0];
            s[nt][1] = ex2(s[nt][1] - mn0); rs0 += s[nt][1];
            s[nt][2] = ex2(s[nt][2] - mn1); rs1 += s[nt][2];
            s[nt][3] = ex2(s[nt][3] - mn1); rs1 += s[nt][3];
        }
        rs0 += __shfl_xor_sync(FM, rs0, 1);
        rs0 += __shfl_xor_sync(FM, rs0, 2);
        rs1 += __shfl_xor_sync(FM, rs1, 1);
        rs1 += __shfl_xor_sync(FM, rs1, 2);
        lr0 = lr0 * a0 + rs0; mr0 = mn0;
        lr1 = lr1 * a1 + rs1; mr1 = mn1;
        #pragma unroll
        for (int nt = 0; nt < 8; nt++) {
            o[nt][0] *= a0; o[nt][1] *= a0;
            o[nt][2] *= a1; o[nt][3] *= a1;
        }

        // O += P @ V : P from S registers, V B-fragments via ldmatrix.trans
        #pragma unroll
        for (int ks = 0; ks < 4; ks++) {
            uint32_t ph[4], pl[4];
            split_pack(s[2*ks][0],   s[2*ks][1],   ph[0], pl[0]);
            split_pack(s[2*ks][2],   s[2*ks][3],   ph[1], pl[1]);
            split_pack(s[2*ks+1][0], s[2*ks+1][1], ph[2], pl[2]);
            split_pack(s[2*ks+1][2], s[2*ks+1][3], ph[3], pl[3]);
            const uint32_t kOfs = (uint32_t)(ks * 16 * PST) * 4;
            #pragma unroll
            for (int ntp = 0; ntp < 4; ntp++) {
                const uint32_t va = vPat + kOfs + (uint32_t)(ntp * 8) * 4;
                uint32_t vh[4], vl[4];
                LDM4T(vh, va);
                LDM4T(vl, va + QLB);
                mma_bf16(o[2*ntp],   ph, vh);
                mma_bf16(o[2*ntp],   ph, vl);
                mma_bf16(o[2*ntp],   pl, vh);
                mma_bf16(o[2*ntp+1], ph, vh + 2);
                mma_bf16(o[2*ntp+1], ph, vl + 2);
                mma_bf16(o[2*ntp+1], pl, vh + 2);
            }
        }
    }

    // epilogue: normalize, write split pairs for the WO GEMM
    const float inv0 = 1.0f / lr0;
    const float inv1 = 1.0f / lr1;
    const size_t ro0 = (rb + qt * 64 + wrow + lq) * KP2 + hb;
    const size_t ro1 = ro0 + 8 * (size_t)KP2;
    #pragma unroll
    for (int nt = 0; nt < 8; nt++) {
        const int pidx = nt * 4 + lr;
        uint32_t hh, ll;
        split_pack(o[nt][0] * inv0, o[nt][1] * inv0, hh, ll);
        Ch[ro0 + pidx] = hh; Cl[ro0 + pidx] = ll;
        split_pack(o[nt][2] * inv1, o[nt][3] * inv1, hh, ll);
        Ch[ro1 + pidx] = hh; Cl[ro1 + pidx] = ll;
    }
}

// ---------------------------------------------------------------------------
extern "C" void kernel_launch(void* const* d_in, const int* in_sizes, int n_in,
                              void* d_out, int out_size) {
    (void)in_sizes; (void)n_in; (void)out_size;
    const float* x  = (const float*)d_in[0];
    const float* wq = (const float*)d_in[1];
    const float* wk = (const float*)d_in[2];
    const float* wv = (const float*)d_in[3];
    const float* wo = (const float*)d_in[4];
    float* out = (float*)d_out;

    uint32_t *xh, *xl, *qh, *ql, *kh, *kl, *vh, *vl, *ch, *cl;
    uint32_t *wqh, *wql, *wkh, *wkl, *wvh, *wvl, *woh, *wol;
    cudaGetSymbolAddress((void**)&xh,  g_xh);
    cudaGetSymbolAddress((void**)&xl,  g_xl);
    cudaGetSymbolAddress((void**)&qh,  g_qh);
    cudaGetSymbolAddress((void**)&ql,  g_ql);
    cudaGetSymbolAddress((void**)&kh,  g_kh);
    cudaGetSymbolAddress((void**)&kl,  g_kl);
    cudaGetSymbolAddress((void**)&vh,  g_vh);
    cudaGetSymbolAddress((void**)&vl,  g_vl);
    cudaGetSymbolAddress((void**)&ch,  g_ch);
    cudaGetSymbolAddress((void**)&cl,  g_cl);
    cudaGetSymbolAddress((void**)&wqh, g_wqh);
    cudaGetSymbolAddress((void**)&wql, g_wql);
    cudaGetSymbolAddress((void**)&wkh, g_wkh);
    cudaGetSymbolAddress((void**)&wkl, g_wkl);
    cudaGetSymbolAddress((void**)&wvh, g_wvh);
    cudaGetSymbolAddress((void**)&wvl, g_wvl);
    cudaGetSymbolAddress((void**)&woh, g_woh);
    cudaGetSymbolAddress((void**)&wol, g_wol);

    const int nx4 = NTOK * Ec / 4;
    const int nw4 = Ec * Ec / 4;
    split_pairs<<<nx4 / 256, 256>>>((const float4*)x,  (uint2*)xh,  (uint2*)xl,  nx4);
    split_pairs<<<nw4 / 256, 256>>>((const float4*)wq, (uint2*)wqh, (uint2*)wql, nw4);
    split_pairs<<<nw4 / 256, 256>>>((const float4*)wk, (uint2*)wkh, (uint2*)wkl, nw4);
    split_pairs<<<nw4 / 256, 256>>>((const float4*)wv, (uint2*)wvh, (uint2*)wvl, nw4);
    split_pairs<<<nw4 / 256, 256>>>((const float4*)wo, (uint2*)woh, (uint2*)wol, nw4);

    cudaFuncSetAttribute(gemm_qkv, cudaFuncAttributeMaxDynamicSharedMemorySize, GEMM_SMEM);
    cudaFuncSetAttribute(gemm_wo,  cudaFuncAttributeMaxDynamicSharedMemorySize, GEMM_SMEM);

    gemm_qkv<<<dim3(Ec / 128, NTOK / 128, 3), 256, GEMM_SMEM>>>(
        xh, xl, wqh, wql, wkh, wkl, wvh, wvl, qh, ql, kh, kl, vh, vl);

    cudaFuncSetAttribute(flash_attn_mma, cudaFuncAttributeMaxDynamicSharedMemorySize, FA_SMEM);
    flash_attn_mma<<<dim3(Sc / 64, Hc, Bc), 128, FA_SMEM>>>(qh, ql, kh, kl, vh, vl, ch, cl);

    gemm_wo<<<dim3(Ec / 128, NTOK / 128), 256, GEMM_SMEM>>>(ch, cl, woh, wol, out);
}

// round 13
// speedup vs baseline: 1.0424x; 1.0204x over previous
#include <cuda_runtime.h>
#include <cstdint>
#include <math.h>

// Problem constants
#define Bc   2
#define Sc   2048
#define Ec   1024
#define Hc   16
#define Dc   64
#define NTOK (Bc*Sc)          // 4096
#define KP2  (Ec/2)           // 512 pairs per row
// attention scale folded into Q at GEMM epilogue, log2 domain: (1/8)*log2(e)
#define QSCALE 0.1803368801111244f

// ---------------------------------------------------------------------------
// Scratch (static __device__ — no allocation allowed)
// ---------------------------------------------------------------------------
__device__ uint32_t g_xh [NTOK*KP2];
__device__ uint32_t g_xl [NTOK*KP2];
__device__ uint32_t g_qh [NTOK*KP2];
__device__ uint32_t g_ql [NTOK*KP2];
__device__ uint32_t g_kh [NTOK*KP2];
__device__ uint32_t g_kl [NTOK*KP2];
__device__ uint32_t g_vh [NTOK*KP2];
__device__ uint32_t g_vl [NTOK*KP2];
__device__ uint32_t g_ch [NTOK*KP2];
__device__ uint32_t g_cl [NTOK*KP2];
__device__ uint32_t g_wqh[Ec*KP2];
__device__ uint32_t g_wql[Ec*KP2];
__device__ uint32_t g_wkh[Ec*KP2];
__device__ uint32_t g_wkl[Ec*KP2];
__device__ uint32_t g_wvh[Ec*KP2];
__device__ uint32_t g_wvl[Ec*KP2];
__device__ uint32_t g_woh[Ec*KP2];
__device__ uint32_t g_wol[Ec*KP2];

// ---------------------------------------------------------------------------
// helpers
// ---------------------------------------------------------------------------
__device__ __forceinline__ void split_pack(float v0, float v1, uint32_t& h, uint32_t& l) {
    const uint32_t u0 = __float_as_uint(v0);
    const uint32_t u1 = __float_as_uint(v1);
    uint32_t hp;
    asm("prmt.b32 %0, %1, %2, 0x7632;" : "=r"(hp) : "r"(u0), "r"(u1));
    const float l0 = v0 - __uint_as_float(u0 & 0xFFFF0000u);
    const float l1 = v1 - __uint_as_float(u1 & 0xFFFF0000u);
    uint32_t lp;
    asm("cvt.rn.bf16x2.f32 %0, %1, %2;" : "=r"(lp) : "f"(l1), "f"(l0));
    h = hp; l = lp;
}

__device__ __forceinline__ float ex2(float x) {
    float y;
    asm("ex2.approx.f32 %0, %1;" : "=f"(y) : "f"(x));
    return y;
}

__device__ __forceinline__ void mma_bf16(float* c, const uint32_t* a, const uint32_t* b) {
    asm volatile(
        "mma.sync.aligned.m16n8k16.row.col.f32.bf16.bf16.f32 "
        "{%0,%1,%2,%3}, {%4,%5,%6,%7}, {%8,%9}, {%0,%1,%2,%3};"
        : "+f"(c[0]), "+f"(c[1]), "+f"(c[2]), "+f"(c[3])
        : "r"(a[0]), "r"(a[1]), "r"(a[2]), "r"(a[3]), "r"(b[0]), "r"(b[1]));
}

#define LDM4(r, addr) \
    asm volatile("ldmatrix.sync.aligned.m8n8.x4.shared.b16 {%0,%1,%2,%3}, [%4];" \
        : "=r"((r)[0]), "=r"((r)[1]), "=r"((r)[2]), "=r"((r)[3]) : "r"(addr))
#define LDM4T(r, addr) \
    asm volatile("ldmatrix.sync.aligned.m8n8.x4.trans.shared.b16 {%0,%1,%2,%3}, [%4];" \
        : "=r"((r)[0]), "=r"((r)[1]), "=r"((r)[2]), "=r"((r)[3]) : "r"(addr))
#define CPA16(dst, src) \
    asm volatile("cp.async.ca.shared.global [%0], [%1], 16;" :: "r"(dst), "l"(src))
#define CPA_COMMIT() asm volatile("cp.async.commit_group;" ::: "memory")

__device__ __forceinline__ uint32_t smem_u32(const void* p) {
    uint32_t a;
    asm("{ .reg .u64 t; cvta.to.shared.u64 t, %1; cvt.u32.u64 %0, t; }"
        : "=r"(a) : "l"(p));
    return a;
}

// ---------------------------------------------------------------------------
// merged split kernel: x + 4 weights in one launch.
// blocks [0, NX4/256)           -> x
// blocks [NX4/256 + i*NW4/256)  -> weight i
// ---------------------------------------------------------------------------
#define NX4 (NTOK*Ec/4)    // 1048576
#define NW4 (Ec*Ec/4)      // 262144
#define XBLK (NX4/256)     // 4096
#define WBLK (NW4/256)     // 1024

__global__ void __launch_bounds__(256) split_all(
    const float4* __restrict__ x,  uint2* __restrict__ xh,  uint2* __restrict__ xl,
    const float4* __restrict__ w0, uint2* __restrict__ w0h, uint2* __restrict__ w0l,
    const float4* __restrict__ w1, uint2* __restrict__ w1h, uint2* __restrict__ w1l,
    const float4* __restrict__ w2, uint2* __restrict__ w2h, uint2* __restrict__ w2l,
    const float4* __restrict__ w3, uint2* __restrict__ w3h, uint2* __restrict__ w3l) {
    const int blk = blockIdx.x;
    const float4* src;
    uint2 *hp, *lp;
    int idx;
    if (blk < XBLK) {
        src = x; hp = xh; lp = xl; idx = blk * 256 + threadIdx.x;
    } else {
        const int wb = blk - XBLK;
        const int wi = wb / WBLK;
        idx = (wb - wi * WBLK) * 256 + threadIdx.x;
        switch (wi) {
            case 0: src = w0; hp = w0h; lp = w0l; break;
            case 1: src = w1; hp = w1h; lp = w1l; break;
            case 2: src = w2; hp = w2h; lp = w2l; break;
            default: src = w3; hp = w3h; lp = w3l; break;
        }
    }
    float4 v = src[idx];
    uint32_t h0, l0, h1, l1;
    split_pack(v.x, v.y, h0, l0);
    split_pack(v.z, v.w, h1, l1);
    hp[idx] = make_uint2(h0, h1);
    lp[idx] = make_uint2(l0, l1);
}

// ---------------------------------------------------------------------------
// 3xBF16 GEMM core: cp.async double-buffered + ldmatrix (R9-proven).
// ---------------------------------------------------------------------------
#define PRS  20
#define NPAN 32
#define ARRU (128*PRS)
#define ARRB (ARRU*4)
#define BUFU (4*ARRU)
#define BUFB (BUFU*4)
#define GEMM_SMEM (2*BUFB)     // 81920 B

template<bool PAIR>
__device__ __forceinline__ void gemm_core(const uint32_t* __restrict__ Ahg,
                                          const uint32_t* __restrict__ Alg,
                                          const uint32_t* __restrict__ Bhg,
                                          const uint32_t* __restrict__ Blg,
                                          uint32_t* __restrict__ Oh,
                                          uint32_t* __restrict__ Ol,
                                          float* __restrict__ Cf,
                                          float oscale) {
    extern __shared__ uint32_t smu[];
    const uint32_t sb = smem_u32(smu);

    const int tid  = threadIdx.x;
    const int wid  = tid >> 5;
    const int lane = tid & 31;
    const int wm   = (wid & 1) * 64;
    const int wn   = (wid >> 1) * 32;
    const int m0   = blockIdx.y * 128;
    const int n0   = blockIdx.x * 128;
    const int lq   = lane >> 2;
    const int lr   = lane & 3;

    const uint32_t* gb[4] = { Ahg + (size_t)m0 * KP2, Alg + (size_t)m0 * KP2,
                              Bhg + (size_t)n0 * KP2, Blg + (size_t)n0 * KP2 };

    const uint32_t aPat = (uint32_t)((wm + (lane & 15)) * PRS + (lane >> 4) * 4) * 4;
    const uint32_t bPat = 2 * ARRB +
        (uint32_t)((wn + (lane & 7) + ((lane >> 4) & 1) * 8) * PRS + ((lane >> 3) & 1) * 4) * 4;

    float acc[4][4][4];
    #pragma unroll
    for (int i = 0; i < 4; i++)
        #pragma unroll
        for (int j = 0; j < 4; j++)
            #pragma unroll
            for (int e = 0; e < 4; e++) acc[i][j][e] = 0.f;

    #define STAGE(p, buf) do {                                                  \
        const int _pb = (p) * 16;                                               \
        _Pragma("unroll")                                                       \
        for (int arr = 0; arr < 4; arr++) {                                     \
            _Pragma("unroll")                                                   \
            for (int j = 0; j < 2; j++) {                                       \
                const int i   = tid + j * 256;                                  \
                const int row = i >> 2;                                         \
                const int c   = (i & 3) * 4;                                    \
                const uint32_t* src = gb[arr] + (size_t)row * KP2 + _pb + c;    \
                const uint32_t dst = sb +                                       \
                    (uint32_t)((buf) * BUFU + arr * ARRU + row * PRS + c) * 4;  \
                CPA16(dst, src);                                                \
            }                                                                   \
        }                                                                       \
        CPA_COMMIT();                                                           \
    } while (0)

    STAGE(0, 0);

    for (int p = 0; p < NPAN; p++) {
        if (p + 1 < NPAN) {
            STAGE(p + 1, (p + 1) & 1);
            asm volatile("cp.async.wait_group 1;" ::: "memory");
        } else {
            asm volatile("cp.async.wait_group 0;" ::: "memory");
        }
        __syncthreads();

        const uint32_t bufB = (uint32_t)(p & 1) * BUFB;

        #pragma unroll
        for (int s2 = 0; s2 < 2; s2++) {
            const uint32_t pbB = (uint32_t)s2 * 32;
            uint32_t ah[4][4], al[4][4];
            const uint32_t aa = sb + bufB + aPat + pbB;
            #pragma unroll
            for (int mt = 0; mt < 4; mt++) {
                LDM4(ah[mt], aa + (uint32_t)(mt * 16 * PRS) * 4);
                LDM4(al[mt], aa + (uint32_t)(mt * 16 * PRS) * 4 + ARRB);
            }
            const uint32_t ba = sb + bufB + bPat + pbB;
            #pragma unroll
            for (int ntp = 0; ntp < 2; ntp++) {
                uint32_t bh[4], bl[4];
                LDM4(bh, ba + (uint32_t)(ntp * 16 * PRS) * 4);
                LDM4(bl, ba + (uint32_t)(ntp * 16 * PRS) * 4 + ARRB);
                #pragma unroll
                for (int mt = 0; mt < 4; mt++) {
                    mma_bf16(acc[mt][2*ntp],   ah[mt], bh);
                    mma_bf16(acc[mt][2*ntp],   ah[mt], bl);
                    mma_bf16(acc[mt][2*ntp],   al[mt], bh);
                    mma_bf16(acc[mt][2*ntp+1], ah[mt], bh + 2);
                    mma_bf16(acc[mt][2*ntp+1], ah[mt], bl + 2);
                    mma_bf16(acc[mt][2*ntp+1], al[mt], bh + 2);
                }
            }
        }
        __syncthreads();
    }

    #pragma unroll
    for (int mt = 0; mt < 4; mt++) {
        const int r0 = m0 + wm + mt * 16 + lq;
        #pragma unroll
        for (int nt = 0; nt < 4; nt++) {
            if (PAIR) {
                const int pidx = ((n0 + wn + nt * 8) >> 1) + lr;
                uint32_t h, l;
                split_pack(acc[mt][nt][0] * oscale, acc[mt][nt][1] * oscale, h, l);
                Oh[(size_t)r0 * KP2 + pidx] = h;
                Ol[(size_t)r0 * KP2 + pidx] = l;
                split_pack(acc[mt][nt][2] * oscale, acc[mt][nt][3] * oscale, h, l);
                Oh[(size_t)(r0 + 8) * KP2 + pidx] = h;
                Ol[(size_t)(r0 + 8) * KP2 + pidx] = l;
            } else {
                const int cc = n0 + wn + nt * 8 + lr * 2;
                *(float2*)&Cf[(size_t)r0 * Ec + cc]       = make_float2(acc[mt][nt][0], acc[mt][nt][1]);
                *(float2*)&Cf[(size_t)(r0 + 8) * Ec + cc] = make_float2(acc[mt][nt][2], acc[mt][nt][3]);
            }
        }
    }
}

__global__ void __launch_bounds__(256, 2) gemm_qkv(
    const uint32_t* __restrict__ xh,  const uint32_t* __restrict__ xl,
    const uint32_t* __restrict__ wqh, const uint32_t* __restrict__ wql,
    const uint32_t* __restrict__ wkh, const uint32_t* __restrict__ wkl,
    const uint32_t* __restrict__ wvh, const uint32_t* __restrict__ wvl,
    uint32_t* __restrict__ qh, uint32_t* __restrict__ ql,
    uint32_t* __restrict__ kh, uint32_t* __restrict__ kl,
    uint32_t* __restrict__ vh, uint32_t* __restrict__ vl) {
    const uint32_t *bh, *bl;
    uint32_t *oh, *ol;
    float sc;
    if (blockIdx.z == 0)      { bh = wqh; bl = wql; oh = qh; ol = ql; sc = QSCALE; }
    else if (blockIdx.z == 1) { bh = wkh; bl = wkl; oh = kh; ol = kl; sc = 1.0f; }
    else                      { bh = wvh; bl = wvl; oh = vh; ol = vl; sc = 1.0f; }
    gemm_core<true>(xh, xl, bh, bl, oh, ol, nullptr, sc);
}

__global__ void __launch_bounds__(256, 2) gemm_wo(
    const uint32_t* __restrict__ ch, const uint32_t* __restrict__ cl,
    const uint32_t* __restrict__ woh, const uint32_t* __restrict__ wol,
    float* __restrict__ out) {
    gemm_core<false>(ch, cl, woh, wol, nullptr, nullptr, out, 1.0f);
}

// ---------------------------------------------------------------------------
// Flash attention, causal, 3xBF16 — R9 geometry (Br=64, 128 thr, 4 CTA/SM).
// K and V staged in SEPARATE cp.async groups: V copy overlaps S + softmax.
// ---------------------------------------------------------------------------
#define PST 36
#define QLB ((uint32_t)(64*PST)*4)        // bytes per array
#define FA_SMEM (6 * 64 * PST * 4)        // 55296 B

__global__ void __launch_bounds__(128, 4) flash_attn_mma(
    const uint32_t* __restrict__ Qh, const uint32_t* __restrict__ Ql,
    const uint32_t* __restrict__ Kh, const uint32_t* __restrict__ Kl,
    const uint32_t* __restrict__ Vh, const uint32_t* __restrict__ Vl,
    uint32_t* __restrict__ Ch, uint32_t* __restrict__ Cl) {
    extern __shared__ uint32_t smu[];
    const uint32_t sbq = smem_u32(smu);

    const int tid  = threadIdx.x;
    const int wid  = tid >> 5;
    const int lane = tid & 31;
    const int lq   = lane >> 2;
    const int lr   = lane & 3;
    const int wrow = wid * 16;

    const int qt = gridDim.x - 1 - blockIdx.x;
    const int h  = blockIdx.y;
    const int b  = blockIdx.z;
    const int hb = h * 32;
    const size_t rb = (size_t)b * Sc;

    const uint32_t aPat = sbq +
        (uint32_t)((wrow + (lane & 15)) * PST + (lane >> 4) * 4) * 4;
    const uint32_t kPat = sbq + 2 * QLB +
        (uint32_t)(((lane & 7) + ((lane >> 4) & 1) * 8) * PST + ((lane >> 3) & 1) * 4) * 4;
    const uint32_t vPat = sbq + 4 * QLB +
        (uint32_t)(((lane & 7) + ((lane >> 3) & 1) * 8) * PST + ((lane >> 4) & 1) * 4) * 4;

    // stage Q via cp.async (falls into the K-wait of tile 0)
    #pragma unroll
    for (int it = 0; it < 4; it++) {
        const int i   = tid + it * 128;
        const int row = i >> 3;
        const int c   = (i & 7) * 4;
        const size_t src = (rb + qt * 64 + row) * KP2 + hb + c;
        const uint32_t dst = sbq + (uint32_t)(row * PST + c) * 4;
        CPA16(dst, Qh + src);
        CPA16(dst + QLB, Ql + src);
    }
    CPA_COMMIT();   // counts toward the first K wait

    float o[8][4];
    #pragma unroll
    for (int nt = 0; nt < 8; nt++)
        #pragma unroll
        for (int e = 0; e < 4; e++) o[nt][e] = 0.f;
    float mr0 = -1e30f, mr1 = -1e30f, lr0 = 0.f, lr1 = 0.f;

    const unsigned FM = 0xffffffffu;

    for (int jt = 0; jt <= qt; jt++) {
        __syncthreads();   // previous iteration done reading K/V smem
        // stage K (own group), then V (own group)
        #pragma unroll
        for (int it = 0; it < 4; it++) {
            const int i   = tid + it * 128;
            const int row = i >> 3;
            const int c   = (i & 7) * 4;
            const size_t src = (rb + jt * 64 + row) * KP2 + hb + c;
            const uint32_t dst = sbq + (uint32_t)(row * PST + c) * 4;
            CPA16(dst + 2 * QLB, Kh + src);
            CPA16(dst + 3 * QLB, Kl + src);
        }
        CPA_COMMIT();
        #pragma unroll
        for (int it = 0; it < 4; it++) {
            const int i   = tid + it * 128;
            const int row = i >> 3;
            const int c   = (i & 7) * 4;
            const size_t src = (rb + jt * 64 + row) * KP2 + hb + c;
            const uint32_t dst = sbq + (uint32_t)(row * PST + c) * 4;
            CPA16(dst + 4 * QLB, Vh + src);
            CPA16(dst + 5 * QLB, Vl + src);
        }
        CPA_COMMIT();
        asm volatile("cp.async.wait_group 1;" ::: "memory");  // K (and Q) ready
        __syncthreads();

        // S = Q @ K^T  (Q pre-scaled into log2 domain)
        float s[8][4];
        #pragma unroll
        for (int nt = 0; nt < 8; nt++)
            #pragma unroll
            for (int e = 0; e < 4; e++) s[nt][e] = 0.f;

        #pragma unroll
        for (int ks = 0; ks < 4; ks++) {
            const uint32_t pbB = (uint32_t)ks * 32;
            uint32_t ah[4], al[4];
            LDM4(ah, aPat + pbB);
            LDM4(al, aPat + QLB + pbB);
            #pragma unroll
            for (int ntp = 0; ntp < 4; ntp++) {
                const uint32_t ka = kPat + (uint32_t)(ntp * 16 * PST) * 4 + pbB;
                uint32_t bh[4], bl[4];
                LDM4(bh, ka);
                LDM4(bl, ka + QLB);
                mma_bf16(s[2*ntp],   ah, bh);
                mma_bf16(s[2*ntp],   ah, bl);
                mma_bf16(s[2*ntp],   al, bh);
                mma_bf16(s[2*ntp+1], ah, bh + 2);
                mma_bf16(s[2*ntp+1], ah, bl + 2);
                mma_bf16(s[2*ntp+1], al, bh + 2);
            }
        }

        // causal mask (scale already folded into Q)
        if (jt == qt) {
            const int row0 = wrow + lq, row1 = wrow + lq + 8;
            #pragma unroll
            for (int nt = 0; nt < 8; nt++) {
                const int c0 = nt * 8 + lr * 2;
                if (c0     > row0) s[nt][0] = -1e30f;
                if (c0 + 1 > row0) s[nt][1] = -1e30f;
                if (c0     > row1) s[nt][2] = -1e30f;
                if (c0 + 1 > row1) s[nt][3] = -1e30f;
            }
        }

        // online softmax (base-2) — overlaps the in-flight V copy
        float mt0 = -1e30f, mt1 = -1e30f;
        #pragma unroll
        for (int nt = 0; nt < 8; nt++) {
            mt0 = fmaxf(mt0, fmaxf(s[nt][0], s[nt][1]));
            mt1 = fmaxf(mt1, fmaxf(s[nt][2], s[nt][3]));
        }
        mt0 = fmaxf(mt0, __shfl_xor_sync(FM, mt0, 1));
        mt0 = fmaxf(mt0, __shfl_xor_sync(FM, mt0, 2));
        mt1 = fmaxf(mt1, __shfl_xor_sync(FM, mt1, 1));
        mt1 = fmaxf(mt1, __shfl_xor_sync(FM, mt1, 2));
        const float mn0 = fmaxf(mr0, mt0);
        const float mn1 = fmaxf(mr1, mt1);
        const float a0 = ex2(mr0 - mn0);
        const float a1 = ex2(mr1 - mn1);
        float rs0 = 0.f, rs1 = 0.f;
        #pragma unroll
        for (int nt = 0; nt < 8; nt++) {
            s[nt][0] = ex2(s[nt][0] - mn0); rs0 += s[nt][0];
            s[nt][1] = ex2(s[nt][1] - mn0); rs0 += s[nt][1];
            s[nt][2] = ex2(s[nt][2] - mn1); rs1 += s[nt][2];
            s[nt][3] = ex2(s[nt][3] - mn1); rs1 += s[nt][3];
        }
        rs0 += __shfl_xor_sync(FM, rs0, 1);
        rs0 += __shfl_xor_sync(FM, rs0, 2);
        rs1 += __shfl_xor_sync(FM, rs1, 1);
        rs1 += __shfl_xor_sync(FM, rs1, 2);
        lr0 = lr0 * a0 + rs0; mr0 = mn0;
        lr1 = lr1 * a1 + rs1; mr1 = mn1;
        #pragma unroll
        for (int nt = 0; nt < 8; nt++) {
            o[nt][0] *= a0; o[nt][1] *= a0;
            o[nt][2] *= a1; o[nt][3] *= a1;
        }

        // V must be resident before PV
        asm volatile("cp.async.wait_group 0;" ::: "memory");
        __syncthreads();

        // O += P @ V : P from S registers, V B-fragments via ldmatrix.trans
        #pragma unroll
        for (int ks = 0; ks < 4; ks++) {
            uint32_t ph[4], pl[4];
            split_pack(s[2*ks][0],   s[2*ks][1],   ph[0], pl[0]);
            split_pack(s[2*ks][2],   s[2*ks][3],   ph[1], pl[1]);
            split_pack(s[2*ks+1][0], s[2*ks+1][1], ph[2], pl[2]);
            split_pack(s[2*ks+1][2], s[2*ks+1][3], ph[3], pl[3]);
            const uint32_t kOfs = (uint32_t)(ks * 16 * PST) * 4;
            #pragma unroll
            for (int ntp = 0; ntp < 4; ntp++) {
                const uint32_t va = vPat + kOfs + (uint32_t)(ntp * 8) * 4;
                uint32_t vh[4], vl[4];
                LDM4T(vh, va);
                LDM4T(vl, va + QLB);
                mma_bf16(o[2*ntp],   ph, vh);
                mma_bf16(o[2*ntp],   ph, vl);
                mma_bf16(o[2*ntp],   pl, vh);
                mma_bf16(o[2*ntp+1], ph, vh + 2);
                mma_bf16(o[2*ntp+1], ph, vl + 2);
                mma_bf16(o[2*ntp+1], pl, vh + 2);
            }
        }
    }

    // epilogue: normalize, write split pairs for the WO GEMM
    const float inv0 = 1.0f / lr0;
    const float inv1 = 1.0f / lr1;
    const size_t ro0 = (rb + qt * 64 + wrow + lq) * KP2 + hb;
    const size_t ro1 = ro0 + 8 * (size_t)KP2;
    #pragma unroll
    for (int nt = 0; nt < 8; nt++) {
        const int pidx = nt * 4 + lr;
        uint32_t hh, ll;
        split_pack(o[nt][0] * inv0, o[nt][1] * inv0, hh, ll);
        Ch[ro0 + pidx] = hh; Cl[ro0 + pidx] = ll;
        split_pack(o[nt][2] * inv1, o[nt][3] * inv1, hh, ll);
        Ch[ro1 + pidx] = hh; Cl[ro1 + pidx] = ll;
    }
}

// ---------------------------------------------------------------------------
extern "C" void kernel_launch(void* const* d_in, const int* in_sizes, int n_in,
                              void* d_out, int out_size) {
    (void)in_sizes; (void)n_in; (void)out_size;
    const float* x  = (const float*)d_in[0];
    const float* wq = (const float*)d_in[1];
    const float* wk = (const float*)d_in[2];
    const float* wv = (const float*)d_in[3];
    const float* wo = (const float*)d_in[4];
    float* out = (float*)d_out;

    uint32_t *xh, *xl, *qh, *ql, *kh, *kl, *vh, *vl, *ch, *cl;
    uint32_t *wqh, *wql, *wkh, *wkl, *wvh, *wvl, *woh, *wol;
    cudaGetSymbolAddress((void**)&xh,  g_xh);
    cudaGetSymbolAddress((void**)&xl,  g_xl);
    cudaGetSymbolAddress((void**)&qh,  g_qh);
    cudaGetSymbolAddress((void**)&ql,  g_ql);
    cudaGetSymbolAddress((void**)&kh,  g_kh);
    cudaGetSymbolAddress((void**)&kl,  g_kl);
    cudaGetSymbolAddress((void**)&vh,  g_vh);
    cudaGetSymbolAddress((void**)&vl,  g_vl);
    cudaGetSymbolAddress((void**)&ch,  g_ch);
    cudaGetSymbolAddress((void**)&cl,  g_cl);
    cudaGetSymbolAddress((void**)&wqh, g_wqh);
    cudaGetSymbolAddress((void**)&wql, g_wql);
    cudaGetSymbolAddress((void**)&wkh, g_wkh);
    cudaGetSymbolAddress((void**)&wkl, g_wkl);
    cudaGetSymbolAddress((void**)&wvh, g_wvh);
    cudaGetSymbolAddress((void**)&wvl, g_wvl);
    cudaGetSymbolAddress((void**)&woh, g_woh);
    cudaGetSymbolAddress((void**)&wol, g_wol);

    // one merged split launch: x + wq + wk + wv + wo
    split_all<<<XBLK + 4 * WBLK, 256>>>(
        (const float4*)x,  (uint2*)xh,  (uint2*)xl,
        (const float4*)wq, (uint2*)wqh, (uint2*)wql,
        (const float4*)wk, (uint2*)wkh, (uint2*)wkl,
        (const float4*)wv, (uint2*)wvh, (uint2*)wvl,
        (const float4*)wo, (uint2*)woh, (uint2*)wol);

    cudaFuncSetAttribute(gemm_qkv, cudaFuncAttributeMaxDynamicSharedMemorySize, GEMM_SMEM);
    cudaFuncSetAttribute(gemm_wo,  cudaFuncAttributeMaxDynamicSharedMemorySize, GEMM_SMEM);

    gemm_qkv<<<dim3(Ec / 128, NTOK / 128, 3), 256, GEMM_SMEM>>>(
        xh, xl, wqh, wql, wkh, wkl, wvh, wvl, qh, ql, kh, kl, vh, vl);

    cudaFuncSetAttribute(flash_attn_mma, cudaFuncAttributeMaxDynamicSharedMemorySize, FA_SMEM);
    flash_attn_mma<<<dim3(Sc / 64, Hc, Bc), 128, FA_SMEM>>>(qh, ql, kh, kl, vh, vl, ch, cl);

    gemm_wo<<<dim3(Ec / 128, NTOK / 128), 256, GEMM_SMEM>>>(ch, cl, woh, wol, out);
}

// round 14
// speedup vs baseline: 1.0751x; 1.0313x over previous
#include <cuda_runtime.h>
#include <cstdint>
#include <math.h>

// Problem constants
#define Bc   2
#define Sc   2048
#define Ec   1024
#define Hc   16
#define Dc   64
#define NTOK (Bc*Sc)          // 4096
#define KP2  (Ec/2)           // 512 pairs per row
// attention scale folded into Q at GEMM epilogue, log2 domain: (1/8)*log2(e)
#define QSCALE 0.1803368801111244f

// ---------------------------------------------------------------------------
// Scratch (static __device__ — no allocation allowed)
// ---------------------------------------------------------------------------
__device__ uint32_t g_xh [NTOK*KP2];
__device__ uint32_t g_xl [NTOK*KP2];
__device__ uint32_t g_qh [NTOK*KP2];
__device__ uint32_t g_ql [NTOK*KP2];
__device__ uint32_t g_kh [NTOK*KP2];
__device__ uint32_t g_kl [NTOK*KP2];
__device__ uint32_t g_vh [NTOK*KP2];
__device__ uint32_t g_vl [NTOK*KP2];
__device__ uint32_t g_ch [NTOK*KP2];
__device__ uint32_t g_cl [NTOK*KP2];
__device__ uint32_t g_wqh[Ec*KP2];
__device__ uint32_t g_wql[Ec*KP2];
__device__ uint32_t g_wkh[Ec*KP2];
__device__ uint32_t g_wkl[Ec*KP2];
__device__ uint32_t g_wvh[Ec*KP2];
__device__ uint32_t g_wvl[Ec*KP2];
__device__ uint32_t g_woh[Ec*KP2];
__device__ uint32_t g_wol[Ec*KP2];

// ---------------------------------------------------------------------------
// helpers
// ---------------------------------------------------------------------------
__device__ __forceinline__ void split_pack(float v0, float v1, uint32_t& h, uint32_t& l) {
    const uint32_t u0 = __float_as_uint(v0);
    const uint32_t u1 = __float_as_uint(v1);
    uint32_t hp;
    asm("prmt.b32 %0, %1, %2, 0x7632;" : "=r"(hp) : "r"(u0), "r"(u1));
    const float l0 = v0 - __uint_as_float(u0 & 0xFFFF0000u);
    const float l1 = v1 - __uint_as_float(u1 & 0xFFFF0000u);
    uint32_t lp;
    asm("cvt.rn.bf16x2.f32 %0, %1, %2;" : "=r"(lp) : "f"(l1), "f"(l0));
    h = hp; l = lp;
}

__device__ __forceinline__ float ex2(float x) {
    float y;
    asm("ex2.approx.f32 %0, %1;" : "=f"(y) : "f"(x));
    return y;
}

__device__ __forceinline__ void mma_bf16(float* c, const uint32_t* a, const uint32_t* b) {
    asm volatile(
        "mma.sync.aligned.m16n8k16.row.col.f32.bf16.bf16.f32 "
        "{%0,%1,%2,%3}, {%4,%5,%6,%7}, {%8,%9}, {%0,%1,%2,%3};"
        : "+f"(c[0]), "+f"(c[1]), "+f"(c[2]), "+f"(c[3])
        : "r"(a[0]), "r"(a[1]), "r"(a[2]), "r"(a[3]), "r"(b[0]), "r"(b[1]));
}

#define LDM4(r, addr) \
    asm volatile("ldmatrix.sync.aligned.m8n8.x4.shared.b16 {%0,%1,%2,%3}, [%4];" \
        : "=r"((r)[0]), "=r"((r)[1]), "=r"((r)[2]), "=r"((r)[3]) : "r"(addr))
#define LDM4T(r, addr) \
    asm volatile("ldmatrix.sync.aligned.m8n8.x4.trans.shared.b16 {%0,%1,%2,%3}, [%4];" \
        : "=r"((r)[0]), "=r"((r)[1]), "=r"((r)[2]), "=r"((r)[3]) : "r"(addr))
#define CPA16(dst, src) \
    asm volatile("cp.async.ca.shared.global [%0], [%1], 16;" :: "r"(dst), "l"(src))
#define CPA_COMMIT() asm volatile("cp.async.commit_group;" ::: "memory")

__device__ __forceinline__ uint32_t smem_u32(const void* p) {
    uint32_t a;
    asm("{ .reg .u64 t; cvta.to.shared.u64 t, %1; cvt.u32.u64 %0, t; }"
        : "=r"(a) : "l"(p));
    return a;
}

// ---------------------------------------------------------------------------
// merged split kernel (R13-proven)
// ---------------------------------------------------------------------------
#define NX4 (NTOK*Ec/4)    // 1048576
#define NW4 (Ec*Ec/4)      // 262144
#define XBLK (NX4/256)     // 4096
#define WBLK (NW4/256)     // 1024

__global__ void __launch_bounds__(256) split_all(
    const float4* __restrict__ x,  uint2* __restrict__ xh,  uint2* __restrict__ xl,
    const float4* __restrict__ w0, uint2* __restrict__ w0h, uint2* __restrict__ w0l,
    const float4* __restrict__ w1, uint2* __restrict__ w1h, uint2* __restrict__ w1l,
    const float4* __restrict__ w2, uint2* __restrict__ w2h, uint2* __restrict__ w2l,
    const float4* __restrict__ w3, uint2* __restrict__ w3h, uint2* __restrict__ w3l) {
    const int blk = blockIdx.x;
    const float4* src;
    uint2 *hp, *lp;
    int idx;
    if (blk < XBLK) {
        src = x; hp = xh; lp = xl; idx = blk * 256 + threadIdx.x;
    } else {
        const int wb = blk - XBLK;
        const int wi = wb / WBLK;
        idx = (wb - wi * WBLK) * 256 + threadIdx.x;
        switch (wi) {
            case 0: src = w0; hp = w0h; lp = w0l; break;
            case 1: src = w1; hp = w1h; lp = w1l; break;
            case 2: src = w2; hp = w2h; lp = w2l; break;
            default: src = w3; hp = w3h; lp = w3l; break;
        }
    }
    float4 v = src[idx];
    uint32_t h0, l0, h1, l1;
    split_pack(v.x, v.y, h0, l0);
    split_pack(v.z, v.w, h1, l1);
    hp[idx] = make_uint2(h0, h1);
    lp[idx] = make_uint2(l0, l1);
}

// ---------------------------------------------------------------------------
// 3xBF16 GEMM: cp.async double-buffered + ldmatrix.
// NEW: 128 threads, 4 warps (2x2), warp tile 64x64 — 6:1 MMA:ldmatrix ratio,
// 32 accumulator chains per warp.
// ---------------------------------------------------------------------------
#define PRS  20
#define NPAN 32
#define ARRU (128*PRS)
#define ARRB (ARRU*4)
#define BUFU (4*ARRU)
#define BUFB (BUFU*4)
#define GEMM_SMEM (2*BUFB)     // 81920 B
#define GTHR 128

template<bool PAIR>
__device__ __forceinline__ void gemm_core(const uint32_t* __restrict__ Ahg,
                                          const uint32_t* __restrict__ Alg,
                                          const uint32_t* __restrict__ Bhg,
                                          const uint32_t* __restrict__ Blg,
                                          uint32_t* __restrict__ Oh,
                                          uint32_t* __restrict__ Ol,
                                          float* __restrict__ Cf,
                                          float oscale) {
    extern __shared__ uint32_t smu[];
    const uint32_t sb = smem_u32(smu);

    const int tid  = threadIdx.x;
    const int wid  = tid >> 5;            // 0..3
    const int lane = tid & 31;
    const int wm   = (wid & 1) * 64;      // 2 m-positions
    const int wn   = (wid >> 1) * 64;     // 2 n-positions
    const int m0   = blockIdx.y * 128;
    const int n0   = blockIdx.x * 128;
    const int lq   = lane >> 2;
    const int lr   = lane & 3;

    const uint32_t* gb[4] = { Ahg + (size_t)m0 * KP2, Alg + (size_t)m0 * KP2,
                              Bhg + (size_t)n0 * KP2, Blg + (size_t)n0 * KP2 };

    const uint32_t aPat = (uint32_t)((wm + (lane & 15)) * PRS + (lane >> 4) * 4) * 4;
    const uint32_t bPat = 2 * ARRB +
        (uint32_t)((wn + (lane & 7) + ((lane >> 4) & 1) * 8) * PRS + ((lane >> 3) & 1) * 4) * 4;

    float acc[4][8][4];
    #pragma unroll
    for (int i = 0; i < 4; i++)
        #pragma unroll
        for (int j = 0; j < 8; j++)
            #pragma unroll
            for (int e = 0; e < 4; e++) acc[i][j][e] = 0.f;

    #define STAGE(p, buf) do {                                                  \
        const int _pb = (p) * 16;                                               \
        _Pragma("unroll")                                                       \
        for (int arr = 0; arr < 4; arr++) {                                     \
            _Pragma("unroll")                                                   \
            for (int j = 0; j < 4; j++) {                                       \
                const int i   = tid + j * GTHR;                                 \
                const int row = i >> 2;                                         \
                const int c   = (i & 3) * 4;                                    \
                const uint32_t* src = gb[arr] + (size_t)row * KP2 + _pb + c;    \
                const uint32_t dst = sb +                                       \
                    (uint32_t)((buf) * BUFU + arr * ARRU + row * PRS + c) * 4;  \
                CPA16(dst, src);                                                \
            }                                                                   \
        }                                                                       \
        CPA_COMMIT();                                                           \
    } while (0)

    STAGE(0, 0);

    for (int p = 0; p < NPAN; p++) {
        if (p + 1 < NPAN) {
            STAGE(p + 1, (p + 1) & 1);
            asm volatile("cp.async.wait_group 1;" ::: "memory");
        } else {
            asm volatile("cp.async.wait_group 0;" ::: "memory");
        }
        __syncthreads();

        const uint32_t bufB = (uint32_t)(p & 1) * BUFB;

        #pragma unroll
        for (int s2 = 0; s2 < 2; s2++) {
            const uint32_t pbB = (uint32_t)s2 * 32;
            uint32_t ah[4][4], al[4][4];
            const uint32_t aa = sb + bufB + aPat + pbB;
            #pragma unroll
            for (int mt = 0; mt < 4; mt++) {
                LDM4(ah[mt], aa + (uint32_t)(mt * 16 * PRS) * 4);
                LDM4(al[mt], aa + (uint32_t)(mt * 16 * PRS) * 4 + ARRB);
            }
            const uint32_t ba = sb + bufB + bPat + pbB;
            #pragma unroll
            for (int ntp = 0; ntp < 4; ntp++) {
                uint32_t bh[4], bl[4];
                LDM4(bh, ba + (uint32_t)(ntp * 16 * PRS) * 4);
                LDM4(bl, ba + (uint32_t)(ntp * 16 * PRS) * 4 + ARRB);
                #pragma unroll
                for (int mt = 0; mt < 4; mt++) {
                    mma_bf16(acc[mt][2*ntp],   ah[mt], bh);
                    mma_bf16(acc[mt][2*ntp],   ah[mt], bl);
                    mma_bf16(acc[mt][2*ntp],   al[mt], bh);
                    mma_bf16(acc[mt][2*ntp+1], ah[mt], bh + 2);
                    mma_bf16(acc[mt][2*ntp+1], ah[mt], bl + 2);
                    mma_bf16(acc[mt][2*ntp+1], al[mt], bh + 2);
                }
            }
        }
        __syncthreads();
    }

    #pragma unroll
    for (int mt = 0; mt < 4; mt++) {
        const int r0 = m0 + wm + mt * 16 + lq;
        #pragma unroll
        for (int nt = 0; nt < 8; nt++) {
            if (PAIR) {
                const int pidx = ((n0 + wn + nt * 8) >> 1) + lr;
                uint32_t h, l;
                split_pack(acc[mt][nt][0] * oscale, acc[mt][nt][1] * oscale, h, l);
                Oh[(size_t)r0 * KP2 + pidx] = h;
                Ol[(size_t)r0 * KP2 + pidx] = l;
                split_pack(acc[mt][nt][2] * oscale, acc[mt][nt][3] * oscale, h, l);
                Oh[(size_t)(r0 + 8) * KP2 + pidx] = h;
                Ol[(size_t)(r0 + 8) * KP2 + pidx] = l;
            } else {
                const int cc = n0 + wn + nt * 8 + lr * 2;
                *(float2*)&Cf[(size_t)r0 * Ec + cc]       = make_float2(acc[mt][nt][0], acc[mt][nt][1]);
                *(float2*)&Cf[(size_t)(r0 + 8) * Ec + cc] = make_float2(acc[mt][nt][2], acc[mt][nt][3]);
            }
        }
    }
}

__global__ void __launch_bounds__(GTHR, 2) gemm_qkv(
    const uint32_t* __restrict__ xh,  const uint32_t* __restrict__ xl,
    const uint32_t* __restrict__ wqh, const uint32_t* __restrict__ wql,
    const uint32_t* __restrict__ wkh, const uint32_t* __restrict__ wkl,
    const uint32_t* __restrict__ wvh, const uint32_t* __restrict__ wvl,
    uint32_t* __restrict__ qh, uint32_t* __restrict__ ql,
    uint32_t* __restrict__ kh, uint32_t* __restrict__ kl,
    uint32_t* __restrict__ vh, uint32_t* __restrict__ vl) {
    const uint32_t *bh, *bl;
    uint32_t *oh, *ol;
    float sc;
    if (blockIdx.z == 0)      { bh = wqh; bl = wql; oh = qh; ol = ql; sc = QSCALE; }
    else if (blockIdx.z == 1) { bh = wkh; bl = wkl; oh = kh; ol = kl; sc = 1.0f; }
    else                      { bh = wvh; bl = wvl; oh = vh; ol = vl; sc = 1.0f; }
    gemm_core<true>(xh, xl, bh, bl, oh, ol, nullptr, sc);
}

__global__ void __launch_bounds__(GTHR, 2) gemm_wo(
    const uint32_t* __restrict__ ch, const uint32_t* __restrict__ cl,
    const uint32_t* __restrict__ woh, const uint32_t* __restrict__ wol,
    float* __restrict__ out) {
    gemm_core<false>(ch, cl, woh, wol, nullptr, nullptr, out, 1.0f);
}

// ---------------------------------------------------------------------------
// Flash attention, causal, 3xBF16 — R13 (unchanged, proven).
// ---------------------------------------------------------------------------
#define PST 36
#define QLB ((uint32_t)(64*PST)*4)        // bytes per array
#define FA_SMEM (6 * 64 * PST * 4)        // 55296 B

__global__ void __launch_bounds__(128, 4) flash_attn_mma(
    const uint32_t* __restrict__ Qh, const uint32_t* __restrict__ Ql,
    const uint32_t* __restrict__ Kh, const uint32_t* __restrict__ Kl,
    const uint32_t* __restrict__ Vh, const uint32_t* __restrict__ Vl,
    uint32_t* __restrict__ Ch, uint32_t* __restrict__ Cl) {
    extern __shared__ uint32_t smu[];
    const uint32_t sbq = smem_u32(smu);

    const int tid  = threadIdx.x;
    const int wid  = tid >> 5;
    const int lane = tid & 31;
    const int lq   = lane >> 2;
    const int lr   = lane & 3;
    const int wrow = wid * 16;

    const int qt = gridDim.x - 1 - blockIdx.x;
    const int h  = blockIdx.y;
    const int b  = blockIdx.z;
    const int hb = h * 32;
    const size_t rb = (size_t)b * Sc;

    const uint32_t aPat = sbq +
        (uint32_t)((wrow + (lane & 15)) * PST + (lane >> 4) * 4) * 4;
    const uint32_t kPat = sbq + 2 * QLB +
        (uint32_t)(((lane & 7) + ((lane >> 4) & 1) * 8) * PST + ((lane >> 3) & 1) * 4) * 4;
    const uint32_t vPat = sbq + 4 * QLB +
        (uint32_t)(((lane & 7) + ((lane >> 3) & 1) * 8) * PST + ((lane >> 4) & 1) * 4) * 4;

    // stage Q via cp.async (falls into the K-wait of tile 0)
    #pragma unroll
    for (int it = 0; it < 4; it++) {
        const int i   = tid + it * 128;
        const int row = i >> 3;
        const int c   = (i & 7) * 4;
        const size_t src = (rb + qt * 64 + row) * KP2 + hb + c;
        const uint32_t dst = sbq + (uint32_t)(row * PST + c) * 4;
        CPA16(dst, Qh + src);
        CPA16(dst + QLB, Ql + src);
    }
    CPA_COMMIT();

    float o[8][4];
    #pragma unroll
    for (int nt = 0; nt < 8; nt++)
        #pragma unroll
        for (int e = 0; e < 4; e++) o[nt][e] = 0.f;
    float mr0 = -1e30f, mr1 = -1e30f, lr0 = 0.f, lr1 = 0.f;

    const unsigned FM = 0xffffffffu;

    for (int jt = 0; jt <= qt; jt++) {
        __syncthreads();
        #pragma unroll
        for (int it = 0; it < 4; it++) {
            const int i   = tid + it * 128;
            const int row = i >> 3;
            const int c   = (i & 7) * 4;
            const size_t src = (rb + jt * 64 + row) * KP2 + hb + c;
            const uint32_t dst = sbq + (uint32_t)(row * PST + c) * 4;
            CPA16(dst + 2 * QLB, Kh + src);
            CPA16(dst + 3 * QLB, Kl + src);
        }
        CPA_COMMIT();
        #pragma unroll
        for (int it = 0; it < 4; it++) {
            const int i   = tid + it * 128;
            const int row = i >> 3;
            const int c   = (i & 7) * 4;
            const size_t src = (rb + jt * 64 + row) * KP2 + hb + c;
            const uint32_t dst = sbq + (uint32_t)(row * PST + c) * 4;
            CPA16(dst + 4 * QLB, Vh + src);
            CPA16(dst + 5 * QLB, Vl + src);
        }
        CPA_COMMIT();
        asm volatile("cp.async.wait_group 1;" ::: "memory");  // K (and Q) ready
        __syncthreads();

        float s[8][4];
        #pragma unroll
        for (int nt = 0; nt < 8; nt++)
            #pragma unroll
            for (int e = 0; e < 4; e++) s[nt][e] = 0.f;

        #pragma unroll
        for (int ks = 0; ks < 4; ks++) {
            const uint32_t pbB = (uint32_t)ks * 32;
            uint32_t ah[4], al[4];
            LDM4(ah, aPat + pbB);
            LDM4(al, aPat + QLB + pbB);
            #pragma unroll
            for (int ntp = 0; ntp < 4; ntp++) {
                const uint32_t ka = kPat + (uint32_t)(ntp * 16 * PST) * 4 + pbB;
                uint32_t bh[4], bl[4];
                LDM4(bh, ka);
                LDM4(bl, ka + QLB);
                mma_bf16(s[2*ntp],   ah, bh);
                mma_bf16(s[2*ntp],   ah, bl);
                mma_bf16(s[2*ntp],   al, bh);
                mma_bf16(s[2*ntp+1], ah, bh + 2);
                mma_bf16(s[2*ntp+1], ah, bl + 2);
                mma_bf16(s[2*ntp+1], al, bh + 2);
            }
        }

        if (jt == qt) {
            const int row0 = wrow + lq, row1 = wrow + lq + 8;
            #pragma unroll
            for (int nt = 0; nt < 8; nt++) {
                const int c0 = nt * 8 + lr * 2;
                if (c0     > row0) s[nt][0] = -1e30f;
                if (c0 + 1 > row0) s[nt][1] = -1e30f;
                if (c0     > row1) s[nt][2] = -1e30f;
                if (c0 + 1 > row1) s[nt][3] = -1e30f;
            }
        }

        float mt0 = -1e30f, mt1 = -1e30f;
        #pragma unroll
        for (int nt = 0; nt < 8; nt++) {
            mt0 = fmaxf(mt0, fmaxf(s[nt][0], s[nt][1]));
            mt1 = fmaxf(mt1, fmaxf(s[nt][2], s[nt][3]));
        }
        mt0 = fmaxf(mt0, __shfl_xor_sync(FM, mt0, 1));
        mt0 = fmaxf(mt0, __shfl_xor_sync(FM, mt0, 2));
        mt1 = fmaxf(mt1, __shfl_xor_sync(FM, mt1, 1));
        mt1 = fmaxf(mt1, __shfl_xor_sync(FM, mt1, 2));
        const float mn0 = fmaxf(mr0, mt0);
        const float mn1 = fmaxf(mr1, mt1);
        const float a0 = ex2(mr0 - mn0);
        const float a1 = ex2(mr1 - mn1);
        float rs0 = 0.f, rs1 = 0.f;
        #pragma unroll
        for (int nt = 0; nt < 8; nt++) {
            s[nt][0] = ex2(s[nt][0] - mn0); rs0 += s[nt][0];
            s[nt][1] = ex2(s[nt][1] - mn0); rs0 += s[nt][1];
            s[nt][2] = ex2(s[nt][2] - mn1); rs1 += s[nt][2];
            s[nt][3] = ex2(s[nt][3] - mn1); rs1 += s[nt][3];
        }
        rs0 += __shfl_xor_sync(FM, rs0, 1);
        rs0 += __shfl_xor_sync(FM, rs0, 2);
        rs1 += __shfl_xor_sync(FM, rs1, 1);
        rs1 += __shfl_xor_sync(FM, rs1, 2);
        lr0 = lr0 * a0 + rs0; mr0 = mn0;
        lr1 = lr1 * a1 + rs1; mr1 = mn1;
        #pragma unroll
        for (int nt = 0; nt < 8; nt++) {
            o[nt][0] *= a0; o[nt][1] *= a0;
            o[nt][2] *= a1; o[nt][3] *= a1;
        }

        asm volatile("cp.async.wait_group 0;" ::: "memory");  // V ready
        __syncthreads();

        #pragma unroll
        for (int ks = 0; ks < 4; ks++) {
            uint32_t ph[4], pl[4];
            split_pack(s[2*ks][0],   s[2*ks][1],   ph[0], pl[0]);
            split_pack(s[2*ks][2],   s[2*ks][3],   ph[1], pl[1]);
            split_pack(s[2*ks+1][0], s[2*ks+1][1], ph[2], pl[2]);
            split_pack(s[2*ks+1][2], s[2*ks+1][3], ph[3], pl[3]);
            const uint32_t kOfs = (uint32_t)(ks * 16 * PST) * 4;
            #pragma unroll
            for (int ntp = 0; ntp < 4; ntp++) {
                const uint32_t va = vPat + kOfs + (uint32_t)(ntp * 8) * 4;
                uint32_t vh[4], vl[4];
                LDM4T(vh, va);
                LDM4T(vl, va + QLB);
                mma_bf16(o[2*ntp],   ph, vh);
                mma_bf16(o[2*ntp],   ph, vl);
                mma_bf16(o[2*ntp],   pl, vh);
                mma_bf16(o[2*ntp+1], ph, vh + 2);
                mma_bf16(o[2*ntp+1], ph, vl + 2);
                mma_bf16(o[2*ntp+1], pl, vh + 2);
            }
        }
    }

    const float inv0 = 1.0f / lr0;
    const float inv1 = 1.0f / lr1;
    const size_t ro0 = (rb + qt * 64 + wrow + lq) * KP2 + hb;
    const size_t ro1 = ro0 + 8 * (size_t)KP2;
    #pragma unroll
    for (int nt = 0; nt < 8; nt++) {
        const int pidx = nt * 4 + lr;
        uint32_t hh, ll;
        split_pack(o[nt][0] * inv0, o[nt][1] * inv0, hh, ll);
        Ch[ro0 + pidx] = hh; Cl[ro0 + pidx] = ll;
        split_pack(o[nt][2] * inv1, o[nt][3] * inv1, hh, ll);
        Ch[ro1 + pidx] = hh; Cl[ro1 + pidx] = ll;
    }
}

// ---------------------------------------------------------------------------
extern "C" void kernel_launch(void* const* d_in, const int* in_sizes, int n_in,
                              void* d_out, int out_size) {
    (void)in_sizes; (void)n_in; (void)out_size;
    const float* x  = (const float*)d_in[0];
    const float* wq = (const float*)d_in[1];
    const float* wk = (const float*)d_in[2];
    const float* wv = (const float*)d_in[3];
    const float* wo = (const float*)d_in[4];
    float* out = (float*)d_out;

    uint32_t *xh, *xl, *qh, *ql, *kh, *kl, *vh, *vl, *ch, *cl;
    uint32_t *wqh, *wql, *wkh, *wkl, *wvh, *wvl, *woh, *wol;
    cudaGetSymbolAddress((void**)&xh,  g_xh);
    cudaGetSymbolAddress((void**)&xl,  g_xl);
    cudaGetSymbolAddress((void**)&qh,  g_qh);
    cudaGetSymbolAddress((void**)&ql,  g_ql);
    cudaGetSymbolAddress((void**)&kh,  g_kh);
    cudaGetSymbolAddress((void**)&kl,  g_kl);
    cudaGetSymbolAddress((void**)&vh,  g_vh);
    cudaGetSymbolAddress((void**)&vl,  g_vl);
    cudaGetSymbolAddress((void**)&ch,  g_ch);
    cudaGetSymbolAddress((void**)&cl,  g_cl);
    cudaGetSymbolAddress((void**)&wqh, g_wqh);
    cudaGetSymbolAddress((void**)&wql, g_wql);
    cudaGetSymbolAddress((void**)&wkh, g_wkh);
    cudaGetSymbolAddress((void**)&wkl, g_wkl);
    cudaGetSymbolAddress((void**)&wvh, g_wvh);
    cudaGetSymbolAddress((void**)&wvl, g_wvl);
    cudaGetSymbolAddress((void**)&woh, g_woh);
    cudaGetSymbolAddress((void**)&wol, g_wol);

    split_all<<<XBLK + 4 * WBLK, 256>>>(
        (const float4*)x,  (uint2*)xh,  (uint2*)xl,
        (const float4*)wq, (uint2*)wqh, (uint2*)wql,
        (const float4*)wk, (uint2*)wkh, (uint2*)wkl,
        (const float4*)wv, (uint2*)wvh, (uint2*)wvl,
        (const float4*)wo, (uint2*)woh, (uint2*)wol);

    cudaFuncSetAttribute(gemm_qkv, cudaFuncAttributeMaxDynamicSharedMemorySize, GEMM_SMEM);
    cudaFuncSetAttribute(gemm_wo,  cudaFuncAttributeMaxDynamicSharedMemorySize, GEMM_SMEM);

    gemm_qkv<<<dim3(Ec / 128, NTOK / 128, 3), GTHR, GEMM_SMEM>>>(
        xh, xl, wqh, wql, wkh, wkl, wvh, wvl, qh, ql, kh, kl, vh, vl);

    cudaFuncSetAttribute(flash_attn_mma, cudaFuncAttributeMaxDynamicSharedMemorySize, FA_SMEM);
    flash_attn_mma<<<dim3(Sc / 64, Hc, Bc), 128, FA_SMEM>>>(qh, ql, kh, kl, vh, vl, ch, cl);

    gemm_wo<<<dim3(Ec / 128, NTOK / 128), GTHR, GEMM_SMEM>>>(ch, cl, woh, wol, out);
}

// round 15
// speedup vs baseline: 1.0771x; 1.0019x over previous
#include <cuda_runtime.h>
#include <cstdint>
#include <math.h>

// Problem constants
#define Bc   2
#define Sc   2048
#define Ec   1024
#define Hc   16
#define Dc   64
#define NTOK (Bc*Sc)          // 4096
#define KP2  (Ec/2)           // 512 pairs per row
// attention scale folded into Q at GEMM epilogue, log2 domain: (1/8)*log2(e)
#define QSCALE 0.1803368801111244f

// ---------------------------------------------------------------------------
// Scratch (static __device__ — no allocation allowed)
// ---------------------------------------------------------------------------
__device__ uint32_t g_xh [NTOK*KP2];
__device__ uint32_t g_xl [NTOK*KP2];
__device__ uint32_t g_qh [NTOK*KP2];
__device__ uint32_t g_ql [NTOK*KP2];
__device__ uint32_t g_kh [NTOK*KP2];
__device__ uint32_t g_kl [NTOK*KP2];
__device__ uint32_t g_vh [NTOK*KP2];
__device__ uint32_t g_vl [NTOK*KP2];
__device__ uint32_t g_ch [NTOK*KP2];
__device__ uint32_t g_cl [NTOK*KP2];
__device__ uint32_t g_wqh[Ec*KP2];
__device__ uint32_t g_wql[Ec*KP2];
__device__ uint32_t g_wkh[Ec*KP2];
__device__ uint32_t g_wkl[Ec*KP2];
__device__ uint32_t g_wvh[Ec*KP2];
__device__ uint32_t g_wvl[Ec*KP2];
__device__ uint32_t g_woh[Ec*KP2];
__device__ uint32_t g_wol[Ec*KP2];

// ---------------------------------------------------------------------------
// helpers
// ---------------------------------------------------------------------------
__device__ __forceinline__ void split_pack(float v0, float v1, uint32_t& h, uint32_t& l) {
    const uint32_t u0 = __float_as_uint(v0);
    const uint32_t u1 = __float_as_uint(v1);
    uint32_t hp;
    asm("prmt.b32 %0, %1, %2, 0x7632;" : "=r"(hp) : "r"(u0), "r"(u1));
    const float l0 = v0 - __uint_as_float(u0 & 0xFFFF0000u);
    const float l1 = v1 - __uint_as_float(u1 & 0xFFFF0000u);
    uint32_t lp;
    asm("cvt.rn.bf16x2.f32 %0, %1, %2;" : "=r"(lp) : "f"(l1), "f"(l0));
    h = hp; l = lp;
}

__device__ __forceinline__ float ex2(float x) {
    float y;
    asm("ex2.approx.f32 %0, %1;" : "=f"(y) : "f"(x));
    return y;
}

__device__ __forceinline__ void mma_bf16(float* c, const uint32_t* a, const uint32_t* b) {
    asm volatile(
        "mma.sync.aligned.m16n8k16.row.col.f32.bf16.bf16.f32 "
        "{%0,%1,%2,%3}, {%4,%5,%6,%7}, {%8,%9}, {%0,%1,%2,%3};"
        : "+f"(c[0]), "+f"(c[1]), "+f"(c[2]), "+f"(c[3])
        : "r"(a[0]), "r"(a[1]), "r"(a[2]), "r"(a[3]), "r"(b[0]), "r"(b[1]));
}

#define LDM4(r, addr) \
    asm volatile("ldmatrix.sync.aligned.m8n8.x4.shared.b16 {%0,%1,%2,%3}, [%4];" \
        : "=r"((r)[0]), "=r"((r)[1]), "=r"((r)[2]), "=r"((r)[3]) : "r"(addr))
#define LDM4T(r, addr) \
    asm volatile("ldmatrix.sync.aligned.m8n8.x4.trans.shared.b16 {%0,%1,%2,%3}, [%4];" \
        : "=r"((r)[0]), "=r"((r)[1]), "=r"((r)[2]), "=r"((r)[3]) : "r"(addr))
#define CPA16(dst, src) \
    asm volatile("cp.async.ca.shared.global [%0], [%1], 16;" :: "r"(dst), "l"(src))
#define CPA_COMMIT() asm volatile("cp.async.commit_group;" ::: "memory")

__device__ __forceinline__ uint32_t smem_u32(const void* p) {
    uint32_t a;
    asm("{ .reg .u64 t; cvta.to.shared.u64 t, %1; cvt.u32.u64 %0, t; }"
        : "=r"(a) : "l"(p));
    return a;
}

// ---------------------------------------------------------------------------
// merged split kernel (R13-proven)
// ---------------------------------------------------------------------------
#define NX4 (NTOK*Ec/4)    // 1048576
#define NW4 (Ec*Ec/4)      // 262144
#define XBLK (NX4/256)     // 4096
#define WBLK (NW4/256)     // 1024

__global__ void __launch_bounds__(256) split_all(
    const float4* __restrict__ x,  uint2* __restrict__ xh,  uint2* __restrict__ xl,
    const float4* __restrict__ w0, uint2* __restrict__ w0h, uint2* __restrict__ w0l,
    const float4* __restrict__ w1, uint2* __restrict__ w1h, uint2* __restrict__ w1l,
    const float4* __restrict__ w2, uint2* __restrict__ w2h, uint2* __restrict__ w2l,
    const float4* __restrict__ w3, uint2* __restrict__ w3h, uint2* __restrict__ w3l) {
    const int blk = blockIdx.x;
    const float4* src;
    uint2 *hp, *lp;
    int idx;
    if (blk < XBLK) {
        src = x; hp = xh; lp = xl; idx = blk * 256 + threadIdx.x;
    } else {
        const int wb = blk - XBLK;
        const int wi = wb / WBLK;
        idx = (wb - wi * WBLK) * 256 + threadIdx.x;
        switch (wi) {
            case 0: src = w0; hp = w0h; lp = w0l; break;
            case 1: src = w1; hp = w1h; lp = w1l; break;
            case 2: src = w2; hp = w2h; lp = w2l; break;
            default: src = w3; hp = w3h; lp = w3l; break;
        }
    }
    float4 v = src[idx];
    uint32_t h0, l0, h1, l1;
    split_pack(v.x, v.y, h0, l0);
    split_pack(v.z, v.w, h1, l1);
    hp[idx] = make_uint2(h0, h1);
    lp[idx] = make_uint2(l0, l1);
}

// ---------------------------------------------------------------------------
// 3xBF16 GEMM: cp.async double-buffered + ldmatrix.
// 128 threads, 4 warps (2x2), warp tile 64x64.
// NEW: 3-pass term scheduling — all hi·hi, then all hi·lo, then all lo·hi,
// so each accumulator is re-touched only after 32 independent MMAs.
// Per-accumulator accumulation order unchanged -> bit-identical results.
// ---------------------------------------------------------------------------
#define PRS  20
#define NPAN 32
#define ARRU (128*PRS)
#define ARRB (ARRU*4)
#define BUFU (4*ARRU)
#define BUFB (BUFU*4)
#define GEMM_SMEM (2*BUFB)     // 81920 B
#define GTHR 128

template<bool PAIR>
__device__ __forceinline__ void gemm_core(const uint32_t* __restrict__ Ahg,
                                          const uint32_t* __restrict__ Alg,
                                          const uint32_t* __restrict__ Bhg,
                                          const uint32_t* __restrict__ Blg,
                                          uint32_t* __restrict__ Oh,
                                          uint32_t* __restrict__ Ol,
                                          float* __restrict__ Cf,
                                          float oscale) {
    extern __shared__ uint32_t smu[];
    const uint32_t sb = smem_u32(smu);

    const int tid  = threadIdx.x;
    const int wid  = tid >> 5;            // 0..3
    const int lane = tid & 31;
    const int wm   = (wid & 1) * 64;
    const int wn   = (wid >> 1) * 64;
    const int m0   = blockIdx.y * 128;
    const int n0   = blockIdx.x * 128;
    const int lq   = lane >> 2;
    const int lr   = lane & 3;

    const uint32_t* gb[4] = { Ahg + (size_t)m0 * KP2, Alg + (size_t)m0 * KP2,
                              Bhg + (size_t)n0 * KP2, Blg + (size_t)n0 * KP2 };

    const uint32_t aPat = (uint32_t)((wm + (lane & 15)) * PRS + (lane >> 4) * 4) * 4;
    const uint32_t bPat = 2 * ARRB +
        (uint32_t)((wn + (lane & 7) + ((lane >> 4) & 1) * 8) * PRS + ((lane >> 3) & 1) * 4) * 4;

    float acc[4][8][4];
    #pragma unroll
    for (int i = 0; i < 4; i++)
        #pragma unroll
        for (int j = 0; j < 8; j++)
            #pragma unroll
            for (int e = 0; e < 4; e++) acc[i][j][e] = 0.f;

    #define STAGE(p, buf) do {                                                  \
        const int _pb = (p) * 16;                                               \
        _Pragma("unroll")                                                       \
        for (int arr = 0; arr < 4; arr++) {                                     \
            _Pragma("unroll")                                                   \
            for (int j = 0; j < 4; j++) {                                       \
                const int i   = tid + j * GTHR;                                 \
                const int row = i >> 2;                                         \
                const int c   = (i & 3) * 4;                                    \
                const uint32_t* src = gb[arr] + (size_t)row * KP2 + _pb + c;    \
                const uint32_t dst = sb +                                       \
                    (uint32_t)((buf) * BUFU + arr * ARRU + row * PRS + c) * 4;  \
                CPA16(dst, src);                                                \
            }                                                                   \
        }                                                                       \
        CPA_COMMIT();                                                           \
    } while (0)

    STAGE(0, 0);

    for (int p = 0; p < NPAN; p++) {
        if (p + 1 < NPAN) {
            STAGE(p + 1, (p + 1) & 1);
            asm volatile("cp.async.wait_group 1;" ::: "memory");
        } else {
            asm volatile("cp.async.wait_group 0;" ::: "memory");
        }
        __syncthreads();

        const uint32_t bufB = (uint32_t)(p & 1) * BUFB;

        #pragma unroll
        for (int s2 = 0; s2 < 2; s2++) {
            const uint32_t pbB = (uint32_t)s2 * 32;
            // load ALL fragments for this k-step
            uint32_t ah[4][4], al[4][4], bh[4][4], bl[4][4];
            const uint32_t aa = sb + bufB + aPat + pbB;
            #pragma unroll
            for (int mt = 0; mt < 4; mt++) {
                LDM4(ah[mt], aa + (uint32_t)(mt * 16 * PRS) * 4);
                LDM4(al[mt], aa + (uint32_t)(mt * 16 * PRS) * 4 + ARRB);
            }
            const uint32_t ba = sb + bufB + bPat + pbB;
            #pragma unroll
            for (int ntp = 0; ntp < 4; ntp++) {
                LDM4(bh[ntp], ba + (uint32_t)(ntp * 16 * PRS) * 4);
                LDM4(bl[ntp], ba + (uint32_t)(ntp * 16 * PRS) * 4 + ARRB);
            }
            // pass 1: hi*hi into all 32 accumulators
            #pragma unroll
            for (int ntp = 0; ntp < 4; ntp++)
                #pragma unroll
                for (int mt = 0; mt < 4; mt++) {
                    mma_bf16(acc[mt][2*ntp],   ah[mt], bh[ntp]);
                    mma_bf16(acc[mt][2*ntp+1], ah[mt], bh[ntp] + 2);
                }
            // pass 2: hi*lo
            #pragma unroll
            for (int ntp = 0; ntp < 4; ntp++)
                #pragma unroll
                for (int mt = 0; mt < 4; mt++) {
                    mma_bf16(acc[mt][2*ntp],   ah[mt], bl[ntp]);
                    mma_bf16(acc[mt][2*ntp+1], ah[mt], bl[ntp] + 2);
                }
            // pass 3: lo*hi
            #pragma unroll
            for (int ntp = 0; ntp < 4; ntp++)
                #pragma unroll
                for (int mt = 0; mt < 4; mt++) {
                    mma_bf16(acc[mt][2*ntp],   al[mt], bh[ntp]);
                    mma_bf16(acc[mt][2*ntp+1], al[mt], bh[ntp] + 2);
                }
        }
        __syncthreads();
    }

    #pragma unroll
    for (int mt = 0; mt < 4; mt++) {
        const int r0 = m0 + wm + mt * 16 + lq;
        #pragma unroll
        for (int nt = 0; nt < 8; nt++) {
            if (PAIR) {
                const int pidx = ((n0 + wn + nt * 8) >> 1) + lr;
                uint32_t h, l;
                split_pack(acc[mt][nt][0] * oscale, acc[mt][nt][1] * oscale, h, l);
                Oh[(size_t)r0 * KP2 + pidx] = h;
                Ol[(size_t)r0 * KP2 + pidx] = l;
                split_pack(acc[mt][nt][2] * oscale, acc[mt][nt][3] * oscale, h, l);
                Oh[(size_t)(r0 + 8) * KP2 + pidx] = h;
                Ol[(size_t)(r0 + 8) * KP2 + pidx] = l;
            } else {
                const int cc = n0 + wn + nt * 8 + lr * 2;
                *(float2*)&Cf[(size_t)r0 * Ec + cc]       = make_float2(acc[mt][nt][0], acc[mt][nt][1]);
                *(float2*)&Cf[(size_t)(r0 + 8) * Ec + cc] = make_float2(acc[mt][nt][2], acc[mt][nt][3]);
            }
        }
    }
}

__global__ void __launch_bounds__(GTHR, 2) gemm_qkv(
    const uint32_t* __restrict__ xh,  const uint32_t* __restrict__ xl,
    const uint32_t* __restrict__ wqh, const uint32_t* __restrict__ wql,
    const uint32_t* __restrict__ wkh, const uint32_t* __restrict__ wkl,
    const uint32_t* __restrict__ wvh, const uint32_t* __restrict__ wvl,
    uint32_t* __restrict__ qh, uint32_t* __restrict__ ql,
    uint32_t* __restrict__ kh, uint32_t* __restrict__ kl,
    uint32_t* __restrict__ vh, uint32_t* __restrict__ vl) {
    const uint32_t *bh, *bl;
    uint32_t *oh, *ol;
    float sc;
    if (blockIdx.z == 0)      { bh = wqh; bl = wql; oh = qh; ol = ql; sc = QSCALE; }
    else if (blockIdx.z == 1) { bh = wkh; bl = wkl; oh = kh; ol = kl; sc = 1.0f; }
    else                      { bh = wvh; bl = wvl; oh = vh; ol = vl; sc = 1.0f; }
    gemm_core<true>(xh, xl, bh, bl, oh, ol, nullptr, sc);
}

__global__ void __launch_bounds__(GTHR, 2) gemm_wo(
    const uint32_t* __restrict__ ch, const uint32_t* __restrict__ cl,
    const uint32_t* __restrict__ woh, const uint32_t* __restrict__ wol,
    float* __restrict__ out) {
    gemm_core<false>(ch, cl, woh, wol, nullptr, nullptr, out, 1.0f);
}

// ---------------------------------------------------------------------------
// Flash attention, causal, 3xBF16 — R14 (unchanged, proven).
// ---------------------------------------------------------------------------
#define PST 36
#define QLB ((uint32_t)(64*PST)*4)        // bytes per array
#define FA_SMEM (6 * 64 * PST * 4)        // 55296 B

__global__ void __launch_bounds__(128, 4) flash_attn_mma(
    const uint32_t* __restrict__ Qh, const uint32_t* __restrict__ Ql,
    const uint32_t* __restrict__ Kh, const uint32_t* __restrict__ Kl,
    const uint32_t* __restrict__ Vh, const uint32_t* __restrict__ Vl,
    uint32_t* __restrict__ Ch, uint32_t* __restrict__ Cl) {
    extern __shared__ uint32_t smu[];
    const uint32_t sbq = smem_u32(smu);

    const int tid  = threadIdx.x;
    const int wid  = tid >> 5;
    const int lane = tid & 31;
    const int lq   = lane >> 2;
    const int lr   = lane & 3;
    const int wrow = wid * 16;

    const int qt = gridDim.x - 1 - blockIdx.x;
    const int h  = blockIdx.y;
    const int b  = blockIdx.z;
    const int hb = h * 32;
    const size_t rb = (size_t)b * Sc;

    const uint32_t aPat = sbq +
        (uint32_t)((wrow + (lane & 15)) * PST + (lane >> 4) * 4) * 4;
    const uint32_t kPat = sbq + 2 * QLB +
        (uint32_t)(((lane & 7) + ((lane >> 4) & 1) * 8) * PST + ((lane >> 3) & 1) * 4) * 4;
    const uint32_t vPat = sbq + 4 * QLB +
        (uint32_t)(((lane & 7) + ((lane >> 3) & 1) * 8) * PST + ((lane >> 4) & 1) * 4) * 4;

    // stage Q via cp.async (falls into the K-wait of tile 0)
    #pragma unroll
    for (int it = 0; it < 4; it++) {
        const int i   = tid + it * 128;
        const int row = i >> 3;
        const int c   = (i & 7) * 4;
        const size_t src = (rb + qt * 64 + row) * KP2 + hb + c;
        const uint32_t dst = sbq + (uint32_t)(row * PST + c) * 4;
        CPA16(dst, Qh + src);
        CPA16(dst + QLB, Ql + src);
    }
    CPA_COMMIT();

    float o[8][4];
    #pragma unroll
    for (int nt = 0; nt < 8; nt++)
        #pragma unroll
        for (int e = 0; e < 4; e++) o[nt][e] = 0.f;
    float mr0 = -1e30f, mr1 = -1e30f, lr0 = 0.f, lr1 = 0.f;

    const unsigned FM = 0xffffffffu;

    for (int jt = 0; jt <= qt; jt++) {
        __syncthreads();
        #pragma unroll
        for (int it = 0; it < 4; it++) {
            const int i   = tid + it * 128;
            const int row = i >> 3;
            const int c   = (i & 7) * 4;
            const size_t src = (rb + jt * 64 + row) * KP2 + hb + c;
            const uint32_t dst = sbq + (uint32_t)(row * PST + c) * 4;
            CPA16(dst + 2 * QLB, Kh + src);
            CPA16(dst + 3 * QLB, Kl + src);
        }
        CPA_COMMIT();
        #pragma unroll
        for (int it = 0; it < 4; it++) {
            const int i   = tid + it * 128;
            const int row = i >> 3;
            const int c   = (i & 7) * 4;
            const size_t src = (rb + jt * 64 + row) * KP2 + hb + c;
            const uint32_t dst = sbq + (uint32_t)(row * PST + c) * 4;
            CPA16(dst + 4 * QLB, Vh + src);
            CPA16(dst + 5 * QLB, Vl + src);
        }
        CPA_COMMIT();
        asm volatile("cp.async.wait_group 1;" ::: "memory");  // K (and Q) ready
        __syncthreads();

        float s[8][4];
        #pragma unroll
        for (int nt = 0; nt < 8; nt++)
            #pragma unroll
            for (int e = 0; e < 4; e++) s[nt][e] = 0.f;

        #pragma unroll
        for (int ks = 0; ks < 4; ks++) {
            const uint32_t pbB = (uint32_t)ks * 32;
            uint32_t ah[4], al[4];
            LDM4(ah, aPat + pbB);
            LDM4(al, aPat + QLB + pbB);
            #pragma unroll
            for (int ntp = 0; ntp < 4; ntp++) {
                const uint32_t ka = kPat + (uint32_t)(ntp * 16 * PST) * 4 + pbB;
                uint32_t bh[4], bl[4];
                LDM4(bh, ka);
                LDM4(bl, ka + QLB);
                mma_bf16(s[2*ntp],   ah, bh);
                mma_bf16(s[2*ntp],   ah, bl);
                mma_bf16(s[2*ntp],   al, bh);
                mma_bf16(s[2*ntp+1], ah, bh + 2);
                mma_bf16(s[2*ntp+1], ah, bl + 2);
                mma_bf16(s[2*ntp+1], al, bh + 2);
            }
        }

        if (jt == qt) {
            const int row0 = wrow + lq, row1 = wrow + lq + 8;
            #pragma unroll
            for (int nt = 0; nt < 8; nt++) {
                const int c0 = nt * 8 + lr * 2;
                if (c0     > row0) s[nt][0] = -1e30f;
                if (c0 + 1 > row0) s[nt][1] = -1e30f;
                if (c0     > row1) s[nt][2] = -1e30f;
                if (c0 + 1 > row1) s[nt][3] = -1e30f;
            }
        }

        float mt0 = -1e30f, mt1 = -1e30f;
        #pragma unroll
        for (int nt = 0; nt < 8; nt++) {
            mt0 = fmaxf(mt0, fmaxf(s[nt][0], s[nt][1]));
            mt1 = fmaxf(mt1, fmaxf(s[nt][2], s[nt][3]));
        }
        mt0 = fmaxf(mt0, __shfl_xor_sync(FM, mt0, 1));
        mt0 = fmaxf(mt0, __shfl_xor_sync(FM, mt0, 2));
        mt1 = fmaxf(mt1, __shfl_xor_sync(FM, mt1, 1));
        mt1 = fmaxf(mt1, __shfl_xor_sync(FM, mt1, 2));
        const float mn0 = fmaxf(mr0, mt0);
        const float mn1 = fmaxf(mr1, mt1);
        const float a0 = ex2(mr0 - mn0);
        const float a1 = ex2(mr1 - mn1);
        float rs0 = 0.f, rs1 = 0.f;
        #pragma unroll
        for (int nt = 0; nt < 8; nt++) {
            s[nt][0] = ex2(s[nt][0] - mn0); rs0 += s[nt][0];
            s[nt][1] = ex2(s[nt][1] - mn0); rs0 += s[nt][1];
            s[nt][2] = ex2(s[nt][2] - mn1); rs1 += s[nt][2];
            s[nt][3] = ex2(s[nt][3] - mn1); rs1 += s[nt][3];
        }
        rs0 += __shfl_xor_sync(FM, rs0, 1);
        rs0 += __shfl_xor_sync(FM, rs0, 2);
        rs1 += __shfl_xor_sync(FM, rs1, 1);
        rs1 += __shfl_xor_sync(FM, rs1, 2);
        lr0 = lr0 * a0 + rs0; mr0 = mn0;
        lr1 = lr1 * a1 + rs1; mr1 = mn1;
        #pragma unroll
        for (int nt = 0; nt < 8; nt++) {
            o[nt][0] *= a0; o[nt][1] *= a0;
            o[nt][2] *= a1; o[nt][3] *= a1;
        }

        asm volatile("cp.async.wait_group 0;" ::: "memory");  // V ready
        __syncthreads();

        #pragma unroll
        for (int ks = 0; ks < 4; ks++) {
            uint32_t ph[4], pl[4];
            split_pack(s[2*ks][0],   s[2*ks][1],   ph[0], pl[0]);
            split_pack(s[2*ks][2],   s[2*ks][3],   ph[1], pl[1]);
            split_pack(s[2*ks+1][0], s[2*ks+1][1], ph[2], pl[2]);
            split_pack(s[2*ks+1][2], s[2*ks+1][3], ph[3], pl[3]);
            const uint32_t kOfs = (uint32_t)(ks * 16 * PST) * 4;
            #pragma unroll
            for (int ntp = 0; ntp < 4; ntp++) {
                const uint32_t va = vPat + kOfs + (uint32_t)(ntp * 8) * 4;
                uint32_t vh[4], vl[4];
                LDM4T(vh, va);
                LDM4T(vl, va + QLB);
                mma_bf16(o[2*ntp],   ph, vh);
                mma_bf16(o[2*ntp],   ph, vl);
                mma_bf16(o[2*ntp],   pl, vh);
                mma_bf16(o[2*ntp+1], ph, vh + 2);
                mma_bf16(o[2*ntp+1], ph, vl + 2);
                mma_bf16(o[2*ntp+1], pl, vh + 2);
            }
        }
    }

    const float inv0 = 1.0f / lr0;
    const float inv1 = 1.0f / lr1;
    const size_t ro0 = (rb + qt * 64 + wrow + lq) * KP2 + hb;
    const size_t ro1 = ro0 + 8 * (size_t)KP2;
    #pragma unroll
    for (int nt = 0; nt < 8; nt++) {
        const int pidx = nt * 4 + lr;
        uint32_t hh, ll;
        split_pack(o[nt][0] * inv0, o[nt][1] * inv0, hh, ll);
        Ch[ro0 + pidx] = hh; Cl[ro0 + pidx] = ll;
        split_pack(o[nt][2] * inv1, o[nt][3] * inv1, hh, ll);
        Ch[ro1 + pidx] = hh; Cl[ro1 + pidx] = ll;
    }
}

// ---------------------------------------------------------------------------
extern "C" void kernel_launch(void* const* d_in, const int* in_sizes, int n_in,
                              void* d_out, int out_size) {
    (void)in_sizes; (void)n_in; (void)out_size;
    const float* x  = (const float*)d_in[0];
    const float* wq = (const float*)d_in[1];
    const float* wk = (const float*)d_in[2];
    const float* wv = (const float*)d_in[3];
    const float* wo = (const float*)d_in[4];
    float* out = (float*)d_out;

    uint32_t *xh, *xl, *qh, *ql, *kh, *kl, *vh, *vl, *ch, *cl;
    uint32_t *wqh, *wql, *wkh, *wkl, *wvh, *wvl, *woh, *wol;
    cudaGetSymbolAddress((void**)&xh,  g_xh);
    cudaGetSymbolAddress((void**)&xl,  g_xl);
    cudaGetSymbolAddress((void**)&qh,  g_qh);
    cudaGetSymbolAddress((void**)&ql,  g_ql);
    cudaGetSymbolAddress((void**)&kh,  g_kh);
    cudaGetSymbolAddress((void**)&kl,  g_kl);
    cudaGetSymbolAddress((void**)&vh,  g_vh);
    cudaGetSymbolAddress((void**)&vl,  g_vl);
    cudaGetSymbolAddress((void**)&ch,  g_ch);
    cudaGetSymbolAddress((void**)&cl,  g_cl);
    cudaGetSymbolAddress((void**)&wqh, g_wqh);
    cudaGetSymbolAddress((void**)&wql, g_wql);
    cudaGetSymbolAddress((void**)&wkh, g_wkh);
    cudaGetSymbolAddress((void**)&wkl, g_wkl);
    cudaGetSymbolAddress((void**)&wvh, g_wvh);
    cudaGetSymbolAddress((void**)&wvl, g_wvl);
    cudaGetSymbolAddress((void**)&woh, g_woh);
    cudaGetSymbolAddress((void**)&wol, g_wol);

    split_all<<<XBLK + 4 * WBLK, 256>>>(
        (const float4*)x,  (uint2*)xh,  (uint2*)xl,
        (const float4*)wq, (uint2*)wqh, (uint2*)wql,
        (const float4*)wk, (uint2*)wkh, (uint2*)wkl,
        (const float4*)wv, (uint2*)wvh, (uint2*)wvl,
        (const float4*)wo, (uint2*)woh, (uint2*)wol);

    cudaFuncSetAttribute(gemm_qkv, cudaFuncAttributeMaxDynamicSharedMemorySize, GEMM_SMEM);
    cudaFuncSetAttribute(gemm_wo,  cudaFuncAttributeMaxDynamicSharedMemorySize, GEMM_SMEM);

    gemm_qkv<<<dim3(Ec / 128, NTOK / 128, 3), GTHR, GEMM_SMEM>>>(
        xh, xl, wqh, wql, wkh, wkl, wvh, wvl, qh, ql, kh, kl, vh, vl);

    cudaFuncSetAttribute(flash_attn_mma, cudaFuncAttributeMaxDynamicSharedMemorySize, FA_SMEM);
    flash_attn_mma<<<dim3(Sc / 64, Hc, Bc), 128, FA_SMEM>>>(qh, ql, kh, kl, vh, vl, ch, cl);

    gemm_wo<<<dim3(Ec / 128, NTOK / 128), GTHR, GEMM_SMEM>>>(ch, cl, woh, wol, out);
}

// round 16
// speedup vs baseline: 1.0892x; 1.0112x over previous
#include <cuda_runtime.h>
#include <cstdint>
#include <math.h>

// Problem constants
#define Bc   2
#define Sc   2048
#define Ec   1024
#define Hc   16
#define Dc   64
#define NTOK (Bc*Sc)          // 4096
#define KP2  (Ec/2)           // 512 pairs per row
// attention scale folded into Q at GEMM epilogue, log2 domain: (1/8)*log2(e)
#define QSCALE 0.1803368801111244f

// ---------------------------------------------------------------------------
// Scratch (static __device__ — no allocation allowed)
// ---------------------------------------------------------------------------
__device__ uint32_t g_xh [NTOK*KP2];
__device__ uint32_t g_xl [NTOK*KP2];
__device__ uint32_t g_qh [NTOK*KP2];
__device__ uint32_t g_ql [NTOK*KP2];
__device__ uint32_t g_kh [NTOK*KP2];
__device__ uint32_t g_kl [NTOK*KP2];
__device__ uint32_t g_vh [NTOK*KP2];
__device__ uint32_t g_vl [NTOK*KP2];
__device__ uint32_t g_ch [NTOK*KP2];
__device__ uint32_t g_cl [NTOK*KP2];
__device__ uint32_t g_wqh[Ec*KP2];
__device__ uint32_t g_wql[Ec*KP2];
__device__ uint32_t g_wkh[Ec*KP2];
__device__ uint32_t g_wkl[Ec*KP2];
__device__ uint32_t g_wvh[Ec*KP2];
__device__ uint32_t g_wvl[Ec*KP2];
__device__ uint32_t g_woh[Ec*KP2];
__device__ uint32_t g_wol[Ec*KP2];

// ---------------------------------------------------------------------------
// helpers
// ---------------------------------------------------------------------------
__device__ __forceinline__ void split_pack(float v0, float v1, uint32_t& h, uint32_t& l) {
    const uint32_t u0 = __float_as_uint(v0);
    const uint32_t u1 = __float_as_uint(v1);
    uint32_t hp;
    asm("prmt.b32 %0, %1, %2, 0x7632;" : "=r"(hp) : "r"(u0), "r"(u1));
    const float l0 = v0 - __uint_as_float(u0 & 0xFFFF0000u);
    const float l1 = v1 - __uint_as_float(u1 & 0xFFFF0000u);
    uint32_t lp;
    asm("cvt.rn.bf16x2.f32 %0, %1, %2;" : "=r"(lp) : "f"(l1), "f"(l0));
    h = hp; l = lp;
}

__device__ __forceinline__ float ex2(float x) {
    float y;
    asm("ex2.approx.f32 %0, %1;" : "=f"(y) : "f"(x));
    return y;
}

__device__ __forceinline__ void mma_bf16(float* c, const uint32_t* a, const uint32_t* b) {
    asm volatile(
        "mma.sync.aligned.m16n8k16.row.col.f32.bf16.bf16.f32 "
        "{%0,%1,%2,%3}, {%4,%5,%6,%7}, {%8,%9}, {%0,%1,%2,%3};"
        : "+f"(c[0]), "+f"(c[1]), "+f"(c[2]), "+f"(c[3])
        : "r"(a[0]), "r"(a[1]), "r"(a[2]), "r"(a[3]), "r"(b[0]), "r"(b[1]));
}

#define LDM4(r, addr) \
    asm volatile("ldmatrix.sync.aligned.m8n8.x4.shared.b16 {%0,%1,%2,%3}, [%4];" \
        : "=r"((r)[0]), "=r"((r)[1]), "=r"((r)[2]), "=r"((r)[3]) : "r"(addr))
#define LDM4T(r, addr) \
    asm volatile("ldmatrix.sync.aligned.m8n8.x4.trans.shared.b16 {%0,%1,%2,%3}, [%4];" \
        : "=r"((r)[0]), "=r"((r)[1]), "=r"((r)[2]), "=r"((r)[3]) : "r"(addr))
#define CPA16(dst, src) \
    asm volatile("cp.async.ca.shared.global [%0], [%1], 16;" :: "r"(dst), "l"(src))
#define CPA_COMMIT() asm volatile("cp.async.commit_group;" ::: "memory")

__device__ __forceinline__ uint32_t smem_u32(const void* p) {
    uint32_t a;
    asm("{ .reg .u64 t; cvta.to.shared.u64 t, %1; cvt.u32.u64 %0, t; }"
        : "=r"(a) : "l"(p));
    return a;
}

// ---------------------------------------------------------------------------
// merged split kernel (R13-proven)
// ---------------------------------------------------------------------------
#define NX4 (NTOK*Ec/4)    // 1048576
#define NW4 (Ec*Ec/4)      // 262144
#define XBLK (NX4/256)     // 4096
#define WBLK (NW4/256)     // 1024

__global__ void __launch_bounds__(256) split_all(
    const float4* __restrict__ x,  uint2* __restrict__ xh,  uint2* __restrict__ xl,
    const float4* __restrict__ w0, uint2* __restrict__ w0h, uint2* __restrict__ w0l,
    const float4* __restrict__ w1, uint2* __restrict__ w1h, uint2* __restrict__ w1l,
    const float4* __restrict__ w2, uint2* __restrict__ w2h, uint2* __restrict__ w2l,
    const float4* __restrict__ w3, uint2* __restrict__ w3h, uint2* __restrict__ w3l) {
    const int blk = blockIdx.x;
    const float4* src;
    uint2 *hp, *lp;
    int idx;
    if (blk < XBLK) {
        src = x; hp = xh; lp = xl; idx = blk * 256 + threadIdx.x;
    } else {
        const int wb = blk - XBLK;
        const int wi = wb / WBLK;
        idx = (wb - wi * WBLK) * 256 + threadIdx.x;
        switch (wi) {
            case 0: src = w0; hp = w0h; lp = w0l; break;
            case 1: src = w1; hp = w1h; lp = w1l; break;
            case 2: src = w2; hp = w2h; lp = w2l; break;
            default: src = w3; hp = w3h; lp = w3l; break;
        }
    }
    float4 v = src[idx];
    uint32_t h0, l0, h1, l1;
    split_pack(v.x, v.y, h0, l0);
    split_pack(v.z, v.w, h1, l1);
    hp[idx] = make_uint2(h0, h1);
    lp[idx] = make_uint2(l0, l1);
}

// ---------------------------------------------------------------------------
// 3xBF16 GEMM: cp.async double-buffered + ldmatrix.
// 128 threads, 4 warps (2x2), warp tile 64x64.
// NEW: single __syncthreads per panel — STAGE(p+1) issued AFTER the barrier
// that retires compute(p-1) on the same buffer; copies overlap compute(p).
// ---------------------------------------------------------------------------
#define PRS  20
#define NPAN 32
#define ARRU (128*PRS)
#define ARRB (ARRU*4)
#define BUFU (4*ARRU)
#define BUFB (BUFU*4)
#define GEMM_SMEM (2*BUFB)     // 81920 B
#define GTHR 128

template<bool PAIR>
__device__ __forceinline__ void gemm_core(const uint32_t* __restrict__ Ahg,
                                          const uint32_t* __restrict__ Alg,
                                          const uint32_t* __restrict__ Bhg,
                                          const uint32_t* __restrict__ Blg,
                                          uint32_t* __restrict__ Oh,
                                          uint32_t* __restrict__ Ol,
                                          float* __restrict__ Cf,
                                          float oscale) {
    extern __shared__ uint32_t smu[];
    const uint32_t sb = smem_u32(smu);

    const int tid  = threadIdx.x;
    const int wid  = tid >> 5;            // 0..3
    const int lane = tid & 31;
    const int wm   = (wid & 1) * 64;
    const int wn   = (wid >> 1) * 64;
    const int m0   = blockIdx.y * 128;
    const int n0   = blockIdx.x * 128;
    const int lq   = lane >> 2;
    const int lr   = lane & 3;

    const uint32_t* gb[4] = { Ahg + (size_t)m0 * KP2, Alg + (size_t)m0 * KP2,
                              Bhg + (size_t)n0 * KP2, Blg + (size_t)n0 * KP2 };

    const uint32_t aPat = (uint32_t)((wm + (lane & 15)) * PRS + (lane >> 4) * 4) * 4;
    const uint32_t bPat = 2 * ARRB +
        (uint32_t)((wn + (lane & 7) + ((lane >> 4) & 1) * 8) * PRS + ((lane >> 3) & 1) * 4) * 4;

    float acc[4][8][4];
    #pragma unroll
    for (int i = 0; i < 4; i++)
        #pragma unroll
        for (int j = 0; j < 8; j++)
            #pragma unroll
            for (int e = 0; e < 4; e++) acc[i][j][e] = 0.f;

    #define STAGE(p, buf) do {                                                  \
        const int _pb = (p) * 16;                                               \
        _Pragma("unroll")                                                       \
        for (int arr = 0; arr < 4; arr++) {                                     \
            _Pragma("unroll")                                                   \
            for (int j = 0; j < 4; j++) {                                       \
                const int i   = tid + j * GTHR;                                 \
                const int row = i >> 2;                                         \
                const int c   = (i & 3) * 4;                                    \
                const uint32_t* src = gb[arr] + (size_t)row * KP2 + _pb + c;    \
                const uint32_t dst = sb +                                       \
                    (uint32_t)((buf) * BUFU + arr * ARRU + row * PRS + c) * 4;  \
                CPA16(dst, src);                                                \
            }                                                                   \
        }                                                                       \
        CPA_COMMIT();                                                           \
    } while (0)

    STAGE(0, 0);

    for (int p = 0; p < NPAN; p++) {
        // exactly one cp.async group outstanding at this point
        asm volatile("cp.async.wait_group 0;" ::: "memory");
        __syncthreads();   // buffer p&1 complete & visible; compute(p-1) retired

        if (p + 1 < NPAN) STAGE(p + 1, (p + 1) & 1);   // overlaps compute(p)

        const uint32_t bufB = (uint32_t)(p & 1) * BUFB;

        #pragma unroll
        for (int s2 = 0; s2 < 2; s2++) {
            const uint32_t pbB = (uint32_t)s2 * 32;
            uint32_t ah[4][4], al[4][4], bh[4][4], bl[4][4];
            const uint32_t aa = sb + bufB + aPat + pbB;
            #pragma unroll
            for (int mt = 0; mt < 4; mt++) {
                LDM4(ah[mt], aa + (uint32_t)(mt * 16 * PRS) * 4);
                LDM4(al[mt], aa + (uint32_t)(mt * 16 * PRS) * 4 + ARRB);
            }
            const uint32_t ba = sb + bufB + bPat + pbB;
            #pragma unroll
            for (int ntp = 0; ntp < 4; ntp++) {
                LDM4(bh[ntp], ba + (uint32_t)(ntp * 16 * PRS) * 4);
                LDM4(bl[ntp], ba + (uint32_t)(ntp * 16 * PRS) * 4 + ARRB);
            }
            #pragma unroll
            for (int ntp = 0; ntp < 4; ntp++)
                #pragma unroll
                for (int mt = 0; mt < 4; mt++) {
                    mma_bf16(acc[mt][2*ntp],   ah[mt], bh[ntp]);
                    mma_bf16(acc[mt][2*ntp+1], ah[mt], bh[ntp] + 2);
                }
            #pragma unroll
            for (int ntp = 0; ntp < 4; ntp++)
                #pragma unroll
                for (int mt = 0; mt < 4; mt++) {
                    mma_bf16(acc[mt][2*ntp],   ah[mt], bl[ntp]);
                    mma_bf16(acc[mt][2*ntp+1], ah[mt], bl[ntp] + 2);
                }
            #pragma unroll
            for (int ntp = 0; ntp < 4; ntp++)
                #pragma unroll
                for (int mt = 0; mt < 4; mt++) {
                    mma_bf16(acc[mt][2*ntp],   al[mt], bh[ntp]);
                    mma_bf16(acc[mt][2*ntp+1], al[mt], bh[ntp] + 2);
                }
        }
    }

    #pragma unroll
    for (int mt = 0; mt < 4; mt++) {
        const int r0 = m0 + wm + mt * 16 + lq;
        #pragma unroll
        for (int nt = 0; nt < 8; nt++) {
            if (PAIR) {
                const int pidx = ((n0 + wn + nt * 8) >> 1) + lr;
                uint32_t h, l;
                split_pack(acc[mt][nt][0] * oscale, acc[mt][nt][1] * oscale, h, l);
                Oh[(size_t)r0 * KP2 + pidx] = h;
                Ol[(size_t)r0 * KP2 + pidx] = l;
                split_pack(acc[mt][nt][2] * oscale, acc[mt][nt][3] * oscale, h, l);
                Oh[(size_t)(r0 + 8) * KP2 + pidx] = h;
                Ol[(size_t)(r0 + 8) * KP2 + pidx] = l;
            } else {
                const int cc = n0 + wn + nt * 8 + lr * 2;
                *(float2*)&Cf[(size_t)r0 * Ec + cc]       = make_float2(acc[mt][nt][0], acc[mt][nt][1]);
                *(float2*)&Cf[(size_t)(r0 + 8) * Ec + cc] = make_float2(acc[mt][nt][2], acc[mt][nt][3]);
            }
        }
    }
}

__global__ void __launch_bounds__(GTHR, 2) gemm_qkv(
    const uint32_t* __restrict__ xh,  const uint32_t* __restrict__ xl,
    const uint32_t* __restrict__ wqh, const uint32_t* __restrict__ wql,
    const uint32_t* __restrict__ wkh, const uint32_t* __restrict__ wkl,
    const uint32_t* __restrict__ wvh, const uint32_t* __restrict__ wvl,
    uint32_t* __restrict__ qh, uint32_t* __restrict__ ql,
    uint32_t* __restrict__ kh, uint32_t* __restrict__ kl,
    uint32_t* __restrict__ vh, uint32_t* __restrict__ vl) {
    const uint32_t *bh, *bl;
    uint32_t *oh, *ol;
    float sc;
    if (blockIdx.z == 0)      { bh = wqh; bl = wql; oh = qh; ol = ql; sc = QSCALE; }
    else if (blockIdx.z == 1) { bh = wkh; bl = wkl; oh = kh; ol = kl; sc = 1.0f; }
    else                      { bh = wvh; bl = wvl; oh = vh; ol = vl; sc = 1.0f; }
    gemm_core<true>(xh, xl, bh, bl, oh, ol, nullptr, sc);
}

__global__ void __launch_bounds__(GTHR, 2) gemm_wo(
    const uint32_t* __restrict__ ch, const uint32_t* __restrict__ cl,
    const uint32_t* __restrict__ woh, const uint32_t* __restrict__ wol,
    float* __restrict__ out) {
    gemm_core<false>(ch, cl, woh, wol, nullptr, nullptr, out, 1.0f);
}

// ---------------------------------------------------------------------------
// Flash attention, causal, 3xBF16 — R14 (unchanged, proven).
// ---------------------------------------------------------------------------
#define PST 36
#define QLB ((uint32_t)(64*PST)*4)        // bytes per array
#define FA_SMEM (6 * 64 * PST * 4)        // 55296 B

__global__ void __launch_bounds__(128, 4) flash_attn_mma(
    const uint32_t* __restrict__ Qh, const uint32_t* __restrict__ Ql,
    const uint32_t* __restrict__ Kh, const uint32_t* __restrict__ Kl,
    const uint32_t* __restrict__ Vh, const uint32_t* __restrict__ Vl,
    uint32_t* __restrict__ Ch, uint32_t* __restrict__ Cl) {
    extern __shared__ uint32_t smu[];
    const uint32_t sbq = smem_u32(smu);

    const int tid  = threadIdx.x;
    const int wid  = tid >> 5;
    const int lane = tid & 31;
    const int lq   = lane >> 2;
    const int lr   = lane & 3;
    const int wrow = wid * 16;

    const int qt = gridDim.x - 1 - blockIdx.x;
    const int h  = blockIdx.y;
    const int b  = blockIdx.z;
    const int hb = h * 32;
    const size_t rb = (size_t)b * Sc;

    const uint32_t aPat = sbq +
        (uint32_t)((wrow + (lane & 15)) * PST + (lane >> 4) * 4) * 4;
    const uint32_t kPat = sbq + 2 * QLB +
        (uint32_t)(((lane & 7) + ((lane >> 4) & 1) * 8) * PST + ((lane >> 3) & 1) * 4) * 4;
    const uint32_t vPat = sbq + 4 * QLB +
        (uint32_t)(((lane & 7) + ((lane >> 3) & 1) * 8) * PST + ((lane >> 4) & 1) * 4) * 4;

    // stage Q via cp.async (falls into the K-wait of tile 0)
    #pragma unroll
    for (int it = 0; it < 4; it++) {
        const int i   = tid + it * 128;
        const int row = i >> 3;
        const int c   = (i & 7) * 4;
        const size_t src = (rb + qt * 64 + row) * KP2 + hb + c;
        const uint32_t dst = sbq + (uint32_t)(row * PST + c) * 4;
        CPA16(dst, Qh + src);
        CPA16(dst + QLB, Ql + src);
    }
    CPA_COMMIT();

    float o[8][4];
    #pragma unroll
    for (int nt = 0; nt < 8; nt++)
        #pragma unroll
        for (int e = 0; e < 4; e++) o[nt][e] = 0.f;
    float mr0 = -1e30f, mr1 = -1e30f, lr0 = 0.f, lr1 = 0.f;

    const unsigned FM = 0xffffffffu;

    for (int jt = 0; jt <= qt; jt++) {
        __syncthreads();
        #pragma unroll
        for (int it = 0; it < 4; it++) {
            const int i   = tid + it * 128;
            const int row = i >> 3;
            const int c   = (i & 7) * 4;
            const size_t src = (rb + jt * 64 + row) * KP2 + hb + c;
            const uint32_t dst = sbq + (uint32_t)(row * PST + c) * 4;
            CPA16(dst + 2 * QLB, Kh + src);
            CPA16(dst + 3 * QLB, Kl + src);
        }
        CPA_COMMIT();
        #pragma unroll
        for (int it = 0; it < 4; it++) {
            const int i   = tid + it * 128;
            const int row = i >> 3;
            const int c   = (i & 7) * 4;
            const size_t src = (rb + jt * 64 + row) * KP2 + hb + c;
            const uint32_t dst = sbq + (uint32_t)(row * PST + c) * 4;
            CPA16(dst + 4 * QLB, Vh + src);
            CPA16(dst + 5 * QLB, Vl + src);
        }
        CPA_COMMIT();
        asm volatile("cp.async.wait_group 1;" ::: "memory");  // K (and Q) ready
        __syncthreads();

        float s[8][4];
        #pragma unroll
        for (int nt = 0; nt < 8; nt++)
            #pragma unroll
            for (int e = 0; e < 4; e++) s[nt][e] = 0.f;

        #pragma unroll
        for (int ks = 0; ks < 4; ks++) {
            const uint32_t pbB = (uint32_t)ks * 32;
            uint32_t ah[4], al[4];
            LDM4(ah, aPat + pbB);
            LDM4(al, aPat + QLB + pbB);
            #pragma unroll
            for (int ntp = 0; ntp < 4; ntp++) {
                const uint32_t ka = kPat + (uint32_t)(ntp * 16 * PST) * 4 + pbB;
                uint32_t bh[4], bl[4];
                LDM4(bh, ka);
                LDM4(bl, ka + QLB);
                mma_bf16(s[2*ntp],   ah, bh);
                mma_bf16(s[2*ntp],   ah, bl);
                mma_bf16(s[2*ntp],   al, bh);
                mma_bf16(s[2*ntp+1], ah, bh + 2);
                mma_bf16(s[2*ntp+1], ah, bl + 2);
                mma_bf16(s[2*ntp+1], al, bh + 2);
            }
        }

        if (jt == qt) {
            const int row0 = wrow + lq, row1 = wrow + lq + 8;
            #pragma unroll
            for (int nt = 0; nt < 8; nt++) {
                const int c0 = nt * 8 + lr * 2;
                if (c0     > row0) s[nt][0] = -1e30f;
                if (c0 + 1 > row0) s[nt][1] = -1e30f;
                if (c0     > row1) s[nt][2] = -1e30f;
                if (c0 + 1 > row1) s[nt][3] = -1e30f;
            }
        }

        float mt0 = -1e30f, mt1 = -1e30f;
        #pragma unroll
        for (int nt = 0; nt < 8; nt++) {
            mt0 = fmaxf(mt0, fmaxf(s[nt][0], s[nt][1]));
            mt1 = fmaxf(mt1, fmaxf(s[nt][2], s[nt][3]));
        }
        mt0 = fmaxf(mt0, __shfl_xor_sync(FM, mt0, 1));
        mt0 = fmaxf(mt0, __shfl_xor_sync(FM, mt0, 2));
        mt1 = fmaxf(mt1, __shfl_xor_sync(FM, mt1, 1));
        mt1 = fmaxf(mt1, __shfl_xor_sync(FM, mt1, 2));
        const float mn0 = fmaxf(mr0, mt0);
        const float mn1 = fmaxf(mr1, mt1);
        const float a0 = ex2(mr0 - mn0);
        const float a1 = ex2(mr1 - mn1);
        float rs0 = 0.f, rs1 = 0.f;
        #pragma unroll
        for (int nt = 0; nt < 8; nt++) {
            s[nt][0] = ex2(s[nt][0] - mn0); rs0 += s[nt][0];
            s[nt][1] = ex2(s[nt][1] - mn0); rs0 += s[nt][1];
            s[nt][2] = ex2(s[nt][2] - mn1); rs1 += s[nt][2];
            s[nt][3] = ex2(s[nt][3] - mn1); rs1 += s[nt][3];
        }
        rs0 += __shfl_xor_sync(FM, rs0, 1);
        rs0 += __shfl_xor_sync(FM, rs0, 2);
        rs1 += __shfl_xor_sync(FM, rs1, 1);
        rs1 += __shfl_xor_sync(FM, rs1, 2);
        lr0 = lr0 * a0 + rs0; mr0 = mn0;
        lr1 = lr1 * a1 + rs1; mr1 = mn1;
        #pragma unroll
        for (int nt = 0; nt < 8; nt++) {
            o[nt][0] *= a0; o[nt][1] *= a0;
            o[nt][2] *= a1; o[nt][3] *= a1;
        }

        asm volatile("cp.async.wait_group 0;" ::: "memory");  // V ready
        __syncthreads();

        #pragma unroll
        for (int ks = 0; ks < 4; ks++) {
            uint32_t ph[4], pl[4];
            split_pack(s[2*ks][0],   s[2*ks][1],   ph[0], pl[0]);
            split_pack(s[2*ks][2],   s[2*ks][3],   ph[1], pl[1]);
            split_pack(s[2*ks+1][0], s[2*ks+1][1], ph[2], pl[2]);
            split_pack(s[2*ks+1][2], s[2*ks+1][3], ph[3], pl[3]);
            const uint32_t kOfs = (uint32_t)(ks * 16 * PST) * 4;
            #pragma unroll
            for (int ntp = 0; ntp < 4; ntp++) {
                const uint32_t va = vPat + kOfs + (uint32_t)(ntp * 8) * 4;
                uint32_t vh[4], vl[4];
                LDM4T(vh, va);
                LDM4T(vl, va + QLB);
                mma_bf16(o[2*ntp],   ph, vh);
                mma_bf16(o[2*ntp],   ph, vl);
                mma_bf16(o[2*ntp],   pl, vh);
                mma_bf16(o[2*ntp+1], ph, vh + 2);
                mma_bf16(o[2*ntp+1], ph, vl + 2);
                mma_bf16(o[2*ntp+1], pl, vh + 2);
            }
        }
    }

    const float inv0 = 1.0f / lr0;
    const float inv1 = 1.0f / lr1;
    const size_t ro0 = (rb + qt * 64 + wrow + lq) * KP2 + hb;
    const size_t ro1 = ro0 + 8 * (size_t)KP2;
    #pragma unroll
    for (int nt = 0; nt < 8; nt++) {
        const int pidx = nt * 4 + lr;
        uint32_t hh, ll;
        split_pack(o[nt][0] * inv0, o[nt][1] * inv0, hh, ll);
        Ch[ro0 + pidx] = hh; Cl[ro0 + pidx] = ll;
        split_pack(o[nt][2] * inv1, o[nt][3] * inv1, hh, ll);
        Ch[ro1 + pidx] = hh; Cl[ro1 + pidx] = ll;
    }
}

// ---------------------------------------------------------------------------
extern "C" void kernel_launch(void* const* d_in, const int* in_sizes, int n_in,
                              void* d_out, int out_size) {
    (void)in_sizes; (void)n_in; (void)out_size;
    const float* x  = (const float*)d_in[0];
    const float* wq = (const float*)d_in[1];
    const float* wk = (const float*)d_in[2];
    const float* wv = (const float*)d_in[3];
    const float* wo = (const float*)d_in[4];
    float* out = (float*)d_out;

    uint32_t *xh, *xl, *qh, *ql, *kh, *kl, *vh, *vl, *ch, *cl;
    uint32_t *wqh, *wql, *wkh, *wkl, *wvh, *wvl, *woh, *wol;
    cudaGetSymbolAddress((void**)&xh,  g_xh);
    cudaGetSymbolAddress((void**)&xl,  g_xl);
    cudaGetSymbolAddress((void**)&qh,  g_qh);
    cudaGetSymbolAddress((void**)&ql,  g_ql);
    cudaGetSymbolAddress((void**)&kh,  g_kh);
    cudaGetSymbolAddress((void**)&kl,  g_kl);
    cudaGetSymbolAddress((void**)&vh,  g_vh);
    cudaGetSymbolAddress((void**)&vl,  g_vl);
    cudaGetSymbolAddress((void**)&ch,  g_ch);
    cudaGetSymbolAddress((void**)&cl,  g_cl);
    cudaGetSymbolAddress((void**)&wqh, g_wqh);
    cudaGetSymbolAddress((void**)&wql, g_wql);
    cudaGetSymbolAddress((void**)&wkh, g_wkh);
    cudaGetSymbolAddress((void**)&wkl, g_wkl);
    cudaGetSymbolAddress((void**)&wvh, g_wvh);
    cudaGetSymbolAddress((void**)&wvl, g_wvl);
    cudaGetSymbolAddress((void**)&woh, g_woh);
    cudaGetSymbolAddress((void**)&wol, g_wol);

    split_all<<<XBLK + 4 * WBLK, 256>>>(
        (const float4*)x,  (uint2*)xh,  (uint2*)xl,
        (const float4*)wq, (uint2*)wqh, (uint2*)wql,
        (const float4*)wk, (uint2*)wkh, (uint2*)wkl,
        (const float4*)wv, (uint2*)wvh, (uint2*)wvl,
        (const float4*)wo, (uint2*)woh, (uint2*)wol);

    cudaFuncSetAttribute(gemm_qkv, cudaFuncAttributeMaxDynamicSharedMemorySize, GEMM_SMEM);
    cudaFuncSetAttribute(gemm_wo,  cudaFuncAttributeMaxDynamicSharedMemorySize, GEMM_SMEM);

    gemm_qkv<<<dim3(Ec / 128, NTOK / 128, 3), GTHR, GEMM_SMEM>>>(
        xh, xl, wqh, wql, wkh, wkl, wvh, wvl, qh, ql, kh, kl, vh, vl);

    cudaFuncSetAttribute(flash_attn_mma, cudaFuncAttributeMaxDynamicSharedMemorySize, FA_SMEM);
    flash_attn_mma<<<dim3(Sc / 64, Hc, Bc), 128, FA_SMEM>>>(qh, ql, kh, kl, vh, vl, ch, cl);

    gemm_wo<<<dim3(Ec / 128, NTOK / 128), GTHR, GEMM_SMEM>>>(ch, cl, woh, wol, out);
}

// round 17
// speedup vs baseline: 1.1566x; 1.0619x over previous
#include <cuda_runtime.h>
#include <cstdint>
#include <math.h>

// Problem constants
#define Bc   2
#define Sc   2048
#define Ec   1024
#define Hc   16
#define Dc   64
#define NTOK (Bc*Sc)          // 4096
#define KP2  (Ec/2)           // 512 pairs per row
// attention scale folded into Q at GEMM epilogue, log2 domain: (1/8)*log2(e)
#define QSCALE 0.1803368801111244f

// ---------------------------------------------------------------------------
// Scratch (static __device__ — no allocation allowed)
// ---------------------------------------------------------------------------
__device__ uint32_t g_xh [NTOK*KP2];
__device__ uint32_t g_xl [NTOK*KP2];
__device__ uint32_t g_qh [NTOK*KP2];
__device__ uint32_t g_ql [NTOK*KP2];
__device__ uint32_t g_kh [NTOK*KP2];
__device__ uint32_t g_kl [NTOK*KP2];
__device__ uint32_t g_vh [NTOK*KP2];
__device__ uint32_t g_vl [NTOK*KP2];
__device__ uint32_t g_ch [NTOK*KP2];
__device__ uint32_t g_cl [NTOK*KP2];
__device__ uint32_t g_wqh[Ec*KP2];
__device__ uint32_t g_wql[Ec*KP2];
__device__ uint32_t g_wkh[Ec*KP2];
__device__ uint32_t g_wkl[Ec*KP2];
__device__ uint32_t g_wvh[Ec*KP2];
__device__ uint32_t g_wvl[Ec*KP2];
__device__ uint32_t g_woh[Ec*KP2];
__device__ uint32_t g_wol[Ec*KP2];

// ---------------------------------------------------------------------------
// helpers
// ---------------------------------------------------------------------------
__device__ __forceinline__ void split_pack(float v0, float v1, uint32_t& h, uint32_t& l) {
    const uint32_t u0 = __float_as_uint(v0);
    const uint32_t u1 = __float_as_uint(v1);
    uint32_t hp;
    asm("prmt.b32 %0, %1, %2, 0x7632;" : "=r"(hp) : "r"(u0), "r"(u1));
    const float l0 = v0 - __uint_as_float(u0 & 0xFFFF0000u);
    const float l1 = v1 - __uint_as_float(u1 & 0xFFFF0000u);
    uint32_t lp;
    asm("cvt.rn.bf16x2.f32 %0, %1, %2;" : "=r"(lp) : "f"(l1), "f"(l0));
    h = hp; l = lp;
}

__device__ __forceinline__ float ex2(float x) {
    float y;
    asm("ex2.approx.f32 %0, %1;" : "=f"(y) : "f"(x));
    return y;
}

__device__ __forceinline__ void mma_bf16(float* c, const uint32_t* a, const uint32_t* b) {
    asm volatile(
        "mma.sync.aligned.m16n8k16.row.col.f32.bf16.bf16.f32 "
        "{%0,%1,%2,%3}, {%4,%5,%6,%7}, {%8,%9}, {%0,%1,%2,%3};"
        : "+f"(c[0]), "+f"(c[1]), "+f"(c[2]), "+f"(c[3])
        : "r"(a[0]), "r"(a[1]), "r"(a[2]), "r"(a[3]), "r"(b[0]), "r"(b[1]));
}

#define LDM4(r, addr) \
    asm volatile("ldmatrix.sync.aligned.m8n8.x4.shared.b16 {%0,%1,%2,%3}, [%4];" \
        : "=r"((r)[0]), "=r"((r)[1]), "=r"((r)[2]), "=r"((r)[3]) : "r"(addr))
#define LDM4T(r, addr) \
    asm volatile("ldmatrix.sync.aligned.m8n8.x4.trans.shared.b16 {%0,%1,%2,%3}, [%4];" \
        : "=r"((r)[0]), "=r"((r)[1]), "=r"((r)[2]), "=r"((r)[3]) : "r"(addr))
#define CPA16(dst, src) \
    asm volatile("cp.async.ca.shared.global [%0], [%1], 16;" :: "r"(dst), "l"(src))
#define CPA_COMMIT() asm volatile("cp.async.commit_group;" ::: "memory")

__device__ __forceinline__ uint32_t smem_u32(const void* p) {
    uint32_t a;
    asm("{ .reg .u64 t; cvta.to.shared.u64 t, %1; cvt.u32.u64 %0, t; }"
        : "=r"(a) : "l"(p));
    return a;
}

// ---------------------------------------------------------------------------
// merged split kernel (R13-proven)
// ---------------------------------------------------------------------------
#define NX4 (NTOK*Ec/4)    // 1048576
#define NW4 (Ec*Ec/4)      // 262144
#define XBLK (NX4/256)     // 4096
#define WBLK (NW4/256)     // 1024

__global__ void __launch_bounds__(256) split_all(
    const float4* __restrict__ x,  uint2* __restrict__ xh,  uint2* __restrict__ xl,
    const float4* __restrict__ w0, uint2* __restrict__ w0h, uint2* __restrict__ w0l,
    const float4* __restrict__ w1, uint2* __restrict__ w1h, uint2* __restrict__ w1l,
    const float4* __restrict__ w2, uint2* __restrict__ w2h, uint2* __restrict__ w2l,
    const float4* __restrict__ w3, uint2* __restrict__ w3h, uint2* __restrict__ w3l) {
    const int blk = blockIdx.x;
    const float4* src;
    uint2 *hp, *lp;
    int idx;
    if (blk < XBLK) {
        src = x; hp = xh; lp = xl; idx = blk * 256 + threadIdx.x;
    } else {
        const int wb = blk - XBLK;
        const int wi = wb / WBLK;
        idx = (wb - wi * WBLK) * 256 + threadIdx.x;
        switch (wi) {
            case 0: src = w0; hp = w0h; lp = w0l; break;
            case 1: src = w1; hp = w1h; lp = w1l; break;
            case 2: src = w2; hp = w2h; lp = w2l; break;
            default: src = w3; hp = w3h; lp = w3l; break;
        }
    }
    float4 v = src[idx];
    uint32_t h0, l0, h1, l1;
    split_pack(v.x, v.y, h0, l0);
    split_pack(v.z, v.w, h1, l1);
    hp[idx] = make_uint2(h0, h1);
    lp[idx] = make_uint2(l0, l1);
}

// ---------------------------------------------------------------------------
// 3xBF16 GEMM: cp.async double-buffered + ldmatrix.
// 128 threads, 4 warps (2x2), warp tile 64x64, 1 barrier per panel.
// NEW: s2=0 fragments loaded BEFORE the next-panel STAGE burst, so the
// tensor pipe starts immediately after the barrier and the cp.async
// issue burst hides under the s2=0 MMA stream.
// ---------------------------------------------------------------------------
#define PRS  20
#define NPAN 32
#define ARRU (128*PRS)
#define ARRB (ARRU*4)
#define BUFU (4*ARRU)
#define BUFB (BUFU*4)
#define GEMM_SMEM (2*BUFB)     // 81920 B
#define GTHR 128

template<bool PAIR>
__device__ __forceinline__ void gemm_core(const uint32_t* __restrict__ Ahg,
                                          const uint32_t* __restrict__ Alg,
                                          const uint32_t* __restrict__ Bhg,
                                          const uint32_t* __restrict__ Blg,
                                          uint32_t* __restrict__ Oh,
                                          uint32_t* __restrict__ Ol,
                                          float* __restrict__ Cf,
                                          float oscale) {
    extern __shared__ uint32_t smu[];
    const uint32_t sb = smem_u32(smu);

    const int tid  = threadIdx.x;
    const int wid  = tid >> 5;            // 0..3
    const int lane = tid & 31;
    const int wm   = (wid & 1) * 64;
    const int wn   = (wid >> 1) * 64;
    const int m0   = blockIdx.y * 128;
    const int n0   = blockIdx.x * 128;
    const int lq   = lane >> 2;
    const int lr   = lane & 3;

    const uint32_t* gb[4] = { Ahg + (size_t)m0 * KP2, Alg + (size_t)m0 * KP2,
                              Bhg + (size_t)n0 * KP2, Blg + (size_t)n0 * KP2 };

    const uint32_t aPat = (uint32_t)((wm + (lane & 15)) * PRS + (lane >> 4) * 4) * 4;
    const uint32_t bPat = 2 * ARRB +
        (uint32_t)((wn + (lane & 7) + ((lane >> 4) & 1) * 8) * PRS + ((lane >> 3) & 1) * 4) * 4;

    float acc[4][8][4];
    #pragma unroll
    for (int i = 0; i < 4; i++)
        #pragma unroll
        for (int j = 0; j < 8; j++)
            #pragma unroll
            for (int e = 0; e < 4; e++) acc[i][j][e] = 0.f;

    #define STAGE(p, buf) do {                                                  \
        const int _pb = (p) * 16;                                               \
        _Pragma("unroll")                                                       \
        for (int arr = 0; arr < 4; arr++) {                                     \
            _Pragma("unroll")                                                   \
            for (int j = 0; j < 4; j++) {                                       \
                const int i   = tid + j * GTHR;                                 \
                const int row = i >> 2;                                         \
                const int c   = (i & 3) * 4;                                    \
                const uint32_t* src = gb[arr] + (size_t)row * KP2 + _pb + c;    \
                const uint32_t dst = sb +                                       \
                    (uint32_t)((buf) * BUFU + arr * ARRU + row * PRS + c) * 4;  \
                CPA16(dst, src);                                                \
            }                                                                   \
        }                                                                       \
        CPA_COMMIT();                                                           \
    } while (0)

    // load all fragments of one K=16 step from buffer base
    #define LOAD_FRAGS(bufB, pbB, ah, al, bh, bl) do {                           \
        const uint32_t aa = sb + (bufB) + aPat + (pbB);                          \
        _Pragma("unroll")                                                        \
        for (int mt = 0; mt < 4; mt++) {                                         \
            LDM4(ah[mt], aa + (uint32_t)(mt * 16 * PRS) * 4);                    \
            LDM4(al[mt], aa + (uint32_t)(mt * 16 * PRS) * 4 + ARRB);             \
        }                                                                        \
        const uint32_t ba = sb + (bufB) + bPat + (pbB);                          \
        _Pragma("unroll")                                                        \
        for (int ntp = 0; ntp < 4; ntp++) {                                      \
            LDM4(bh[ntp], ba + (uint32_t)(ntp * 16 * PRS) * 4);                  \
            LDM4(bl[ntp], ba + (uint32_t)(ntp * 16 * PRS) * 4 + ARRB);           \
        }                                                                        \
    } while (0)

    #define DO_MMAS(ah, al, bh, bl) do {                                         \
        _Pragma("unroll")                                                        \
        for (int ntp = 0; ntp < 4; ntp++)                                        \
            _Pragma("unroll")                                                    \
            for (int mt = 0; mt < 4; mt++) {                                     \
                mma_bf16(acc[mt][2*ntp],   ah[mt], bh[ntp]);                     \
                mma_bf16(acc[mt][2*ntp+1], ah[mt], bh[ntp] + 2);                 \
            }                                                                    \
        _Pragma("unroll")                                                        \
        for (int ntp = 0; ntp < 4; ntp++)                                        \
            _Pragma("unroll")                                                    \
            for (int mt = 0; mt < 4; mt++) {                                     \
                mma_bf16(acc[mt][2*ntp],   ah[mt], bl[ntp]);                     \
                mma_bf16(acc[mt][2*ntp+1], ah[mt], bl[ntp] + 2);                 \
            }                                                                    \
        _Pragma("unroll")                                                        \
        for (int ntp = 0; ntp < 4; ntp++)                                        \
            _Pragma("unroll")                                                    \
            for (int mt = 0; mt < 4; mt++) {                                     \
                mma_bf16(acc[mt][2*ntp],   al[mt], bh[ntp]);                     \
                mma_bf16(acc[mt][2*ntp+1], al[mt], bh[ntp] + 2);                 \
            }                                                                    \
    } while (0)

    STAGE(0, 0);

    for (int p = 0; p < NPAN; p++) {
        asm volatile("cp.async.wait_group 0;" ::: "memory");
        __syncthreads();   // buffer p&1 complete & visible; compute(p-1) retired

        const uint32_t bufB = (uint32_t)(p & 1) * BUFB;

        // s2=0 fragments FIRST (data ready) — tensor pipe can start now
        uint32_t ah[4][4], al[4][4], bh[4][4], bl[4][4];
        LOAD_FRAGS(bufB, 0u, ah, al, bh, bl);

        // next-panel copies issue behind the fragment loads, hide under MMAs
        if (p + 1 < NPAN) STAGE(p + 1, (p + 1) & 1);

        DO_MMAS(ah, al, bh, bl);

        // s2=1
        LOAD_FRAGS(bufB, 32u, ah, al, bh, bl);
        DO_MMAS(ah, al, bh, bl);
    }

    #pragma unroll
    for (int mt = 0; mt < 4; mt++) {
        const int r0 = m0 + wm + mt * 16 + lq;
        #pragma unroll
        for (int nt = 0; nt < 8; nt++) {
            if (PAIR) {
                const int pidx = ((n0 + wn + nt * 8) >> 1) + lr;
                uint32_t h, l;
                split_pack(acc[mt][nt][0] * oscale, acc[mt][nt][1] * oscale, h, l);
                Oh[(size_t)r0 * KP2 + pidx] = h;
                Ol[(size_t)r0 * KP2 + pidx] = l;
                split_pack(acc[mt][nt][2] * oscale, acc[mt][nt][3] * oscale, h, l);
                Oh[(size_t)(r0 + 8) * KP2 + pidx] = h;
                Ol[(size_t)(r0 + 8) * KP2 + pidx] = l;
            } else {
                const int cc = n0 + wn + nt * 8 + lr * 2;
                *(float2*)&Cf[(size_t)r0 * Ec + cc]       = make_float2(acc[mt][nt][0], acc[mt][nt][1]);
                *(float2*)&Cf[(size_t)(r0 + 8) * Ec + cc] = make_float2(acc[mt][nt][2], acc[mt][nt][3]);
            }
        }
    }
}

__global__ void __launch_bounds__(GTHR, 2) gemm_qkv(
    const uint32_t* __restrict__ xh,  const uint32_t* __restrict__ xl,
    const uint32_t* __restrict__ wqh, const uint32_t* __restrict__ wql,
    const uint32_t* __restrict__ wkh, const uint32_t* __restrict__ wkl,
    const uint32_t* __restrict__ wvh, const uint32_t* __restrict__ wvl,
    uint32_t* __restrict__ qh, uint32_t* __restrict__ ql,
    uint32_t* __restrict__ kh, uint32_t* __restrict__ kl,
    uint32_t* __restrict__ vh, uint32_t* __restrict__ vl) {
    const uint32_t *bh, *bl;
    uint32_t *oh, *ol;
    float sc;
    if (blockIdx.z == 0)      { bh = wqh; bl = wql; oh = qh; ol = ql; sc = QSCALE; }
    else if (blockIdx.z == 1) { bh = wkh; bl = wkl; oh = kh; ol = kl; sc = 1.0f; }
    else                      { bh = wvh; bl = wvl; oh = vh; ol = vl; sc = 1.0f; }
    gemm_core<true>(xh, xl, bh, bl, oh, ol, nullptr, sc);
}

__global__ void __launch_bounds__(GTHR, 2) gemm_wo(
    const uint32_t* __restrict__ ch, const uint32_t* __restrict__ cl,
    const uint32_t* __restrict__ woh, const uint32_t* __restrict__ wol,
    float* __restrict__ out) {
    gemm_core<false>(ch, cl, woh, wol, nullptr, nullptr, out, 1.0f);
}

// ---------------------------------------------------------------------------
// Flash attention, causal, 3xBF16 — R16 (unchanged, proven).
// ---------------------------------------------------------------------------
#define PST 36
#define QLB ((uint32_t)(64*PST)*4)        // bytes per array
#define FA_SMEM (6 * 64 * PST * 4)        // 55296 B

__global__ void __launch_bounds__(128, 4) flash_attn_mma(
    const uint32_t* __restrict__ Qh, const uint32_t* __restrict__ Ql,
    const uint32_t* __restrict__ Kh, const uint32_t* __restrict__ Kl,
    const uint32_t* __restrict__ Vh, const uint32_t* __restrict__ Vl,
    uint32_t* __restrict__ Ch, uint32_t* __restrict__ Cl) {
    extern __shared__ uint32_t smu[];
    const uint32_t sbq = smem_u32(smu);

    const int tid  = threadIdx.x;
    const int wid  = tid >> 5;
    const int lane = tid & 31;
    const int lq   = lane >> 2;
    const int lr   = lane & 3;
    const int wrow = wid * 16;

    const int qt = gridDim.x - 1 - blockIdx.x;
    const int h  = blockIdx.y;
    const int b  = blockIdx.z;
    const int hb = h * 32;
    const size_t rb = (size_t)b * Sc;

    const uint32_t aPat = sbq +
        (uint32_t)((wrow + (lane & 15)) * PST + (lane >> 4) * 4) * 4;
    const uint32_t kPat = sbq + 2 * QLB +
        (uint32_t)(((lane & 7) + ((lane >> 4) & 1) * 8) * PST + ((lane >> 3) & 1) * 4) * 4;
    const uint32_t vPat = sbq + 4 * QLB +
        (uint32_t)(((lane & 7) + ((lane >> 3) & 1) * 8) * PST + ((lane >> 4) & 1) * 4) * 4;

    // stage Q via cp.async (falls into the K-wait of tile 0)
    #pragma unroll
    for (int it = 0; it < 4; it++) {
        const int i   = tid + it * 128;
        const int row = i >> 3;
        const int c   = (i & 7) * 4;
        const size_t src = (rb + qt * 64 + row) * KP2 + hb + c;
        const uint32_t dst = sbq + (uint32_t)(row * PST + c) * 4;
        CPA16(dst, Qh + src);
        CPA16(dst + QLB, Ql + src);
    }
    CPA_COMMIT();

    float o[8][4];
    #pragma unroll
    for (int nt = 0; nt < 8; nt++)
        #pragma unroll
        for (int e = 0; e < 4; e++) o[nt][e] = 0.f;
    float mr0 = -1e30f, mr1 = -1e30f, lr0 = 0.f, lr1 = 0.f;

    const unsigned FM = 0xffffffffu;

    for (int jt = 0; jt <= qt; jt++) {
        __syncthreads();
        #pragma unroll
        for (int it = 0; it < 4; it++) {
            const int i   = tid + it * 128;
            const int row = i >> 3;
            const int c   = (i & 7) * 4;
            const size_t src = (rb + jt * 64 + row) * KP2 + hb + c;
            const uint32_t dst = sbq + (uint32_t)(row * PST + c) * 4;
            CPA16(dst + 2 * QLB, Kh + src);
            CPA16(dst + 3 * QLB, Kl + src);
        }
        CPA_COMMIT();
        #pragma unroll
        for (int it = 0; it < 4; it++) {
            const int i   = tid + it * 128;
            const int row = i >> 3;
            const int c   = (i & 7) * 4;
            const size_t src = (rb + jt * 64 + row) * KP2 + hb + c;
            const uint32_t dst = sbq + (uint32_t)(row * PST + c) * 4;
            CPA16(dst + 4 * QLB, Vh + src);
            CPA16(dst + 5 * QLB, Vl + src);
        }
        CPA_COMMIT();
        asm volatile("cp.async.wait_group 1;" ::: "memory");  // K (and Q) ready
        __syncthreads();

        float s[8][4];
        #pragma unroll
        for (int nt = 0; nt < 8; nt++)
            #pragma unroll
            for (int e = 0; e < 4; e++) s[nt][e] = 0.f;

        #pragma unroll
        for (int ks = 0; ks < 4; ks++) {
            const uint32_t pbB = (uint32_t)ks * 32;
            uint32_t ah[4], al[4];
            LDM4(ah, aPat + pbB);
            LDM4(al, aPat + QLB + pbB);
            #pragma unroll
            for (int ntp = 0; ntp < 4; ntp++) {
                const uint32_t ka = kPat + (uint32_t)(ntp * 16 * PST) * 4 + pbB;
                uint32_t bh[4], bl[4];
                LDM4(bh, ka);
                LDM4(bl, ka + QLB);
                mma_bf16(s[2*ntp],   ah, bh);
                mma_bf16(s[2*ntp],   ah, bl);
                mma_bf16(s[2*ntp],   al, bh);
                mma_bf16(s[2*ntp+1], ah, bh + 2);
                mma_bf16(s[2*ntp+1], ah, bl + 2);
                mma_bf16(s[2*ntp+1], al, bh + 2);
            }
        }

        if (jt == qt) {
            const int row0 = wrow + lq, row1 = wrow + lq + 8;
            #pragma unroll
            for (int nt = 0; nt < 8; nt++) {
                const int c0 = nt * 8 + lr * 2;
                if (c0     > row0) s[nt][0] = -1e30f;
                if (c0 + 1 > row0) s[nt][1] = -1e30f;
                if (c0     > row1) s[nt][2] = -1e30f;
                if (c0 + 1 > row1) s[nt][3] = -1e30f;
            }
        }

        float mt0 = -1e30f, mt1 = -1e30f;
        #pragma unroll
        for (int nt = 0; nt < 8; nt++) {
            mt0 = fmaxf(mt0, fmaxf(s[nt][0], s[nt][1]));
            mt1 = fmaxf(mt1, fmaxf(s[nt][2], s[nt][3]));
        }
        mt0 = fmaxf(mt0, __shfl_xor_sync(FM, mt0, 1));
        mt0 = fmaxf(mt0, __shfl_xor_sync(FM, mt0, 2));
        mt1 = fmaxf(mt1, __shfl_xor_sync(FM, mt1, 1));
        mt1 = fmaxf(mt1, __shfl_xor_sync(FM, mt1, 2));
        const float mn0 = fmaxf(mr0, mt0);
        const float mn1 = fmaxf(mr1, mt1);
        const float a0 = ex2(mr0 - mn0);
        const float a1 = ex2(mr1 - mn1);
        float rs0 = 0.f, rs1 = 0.f;
        #pragma unroll
        for (int nt = 0; nt < 8; nt++) {
            s[nt][0] = ex2(s[nt][0] - mn0); rs0 += s[nt][0];
            s[nt][1] = ex2(s[nt][1] - mn0); rs0 += s[nt][1];
            s[nt][2] = ex2(s[nt][2] - mn1); rs1 += s[nt][2];
            s[nt][3] = ex2(s[nt][3] - mn1); rs1 += s[nt][3];
        }
        rs0 += __shfl_xor_sync(FM, rs0, 1);
        rs0 += __shfl_xor_sync(FM, rs0, 2);
        rs1 += __shfl_xor_sync(FM, rs1, 1);
        rs1 += __shfl_xor_sync(FM, rs1, 2);
        lr0 = lr0 * a0 + rs0; mr0 = mn0;
        lr1 = lr1 * a1 + rs1; mr1 = mn1;
        #pragma unroll
        for (int nt = 0; nt < 8; nt++) {
            o[nt][0] *= a0; o[nt][1] *= a0;
            o[nt][2] *= a1; o[nt][3] *= a1;
        }

        asm volatile("cp.async.wait_group 0;" ::: "memory");  // V ready
        __syncthreads();

        #pragma unroll
        for (int ks = 0; ks < 4; ks++) {
            uint32_t ph[4], pl[4];
            split_pack(s[2*ks][0],   s[2*ks][1],   ph[0], pl[0]);
            split_pack(s[2*ks][2],   s[2*ks][3],   ph[1], pl[1]);
            split_pack(s[2*ks+1][0], s[2*ks+1][1], ph[2], pl[2]);
            split_pack(s[2*ks+1][2], s[2*ks+1][3], ph[3], pl[3]);
            const uint32_t kOfs = (uint32_t)(ks * 16 * PST) * 4;
            #pragma unroll
            for (int ntp = 0; ntp < 4; ntp++) {
                const uint32_t va = vPat + kOfs + (uint32_t)(ntp * 8) * 4;
                uint32_t vh[4], vl[4];
                LDM4T(vh, va);
                LDM4T(vl, va + QLB);
                mma_bf16(o[2*ntp],   ph, vh);
                mma_bf16(o[2*ntp],   ph, vl);
                mma_bf16(o[2*ntp],   pl, vh);
                mma_bf16(o[2*ntp+1], ph, vh + 2);
                mma_bf16(o[2*ntp+1], ph, vl + 2);
                mma_bf16(o[2*ntp+1], pl, vh + 2);
            }
        }
    }

    const float inv0 = 1.0f / lr0;
    const float inv1 = 1.0f / lr1;
    const size_t ro0 = (rb + qt * 64 + wrow + lq) * KP2 + hb;
    const size_t ro1 = ro0 + 8 * (size_t)KP2;
    #pragma unroll
    for (int nt = 0; nt < 8; nt++) {
        const int pidx = nt * 4 + lr;
        uint32_t hh, ll;
        split_pack(o[nt][0] * inv0, o[nt][1] * inv0, hh, ll);
        Ch[ro0 + pidx] = hh; Cl[ro0 + pidx] = ll;
        split_pack(o[nt][2] * inv1, o[nt][3] * inv1, hh, ll);
        Ch[ro1 + pidx] = hh; Cl[ro1 + pidx] = ll;
    }
}

// ---------------------------------------------------------------------------
extern "C" void kernel_launch(void* const* d_in, const int* in_sizes, int n_in,
                              void* d_out, int out_size) {
    (void)in_sizes; (void)n_in; (void)out_size;
    const float* x  = (const float*)d_in[0];
    const float* wq = (const float*)d_in[1];
    const float* wk = (const float*)d_in[2];
    const float* wv = (const float*)d_in[3];
    const float* wo = (const float*)d_in[4];
    float* out = (float*)d_out;

    uint32_t *xh, *xl, *qh, *ql, *kh, *kl, *vh, *vl, *ch, *cl;
    uint32_t *wqh, *wql, *wkh, *wkl, *wvh, *wvl, *woh, *wol;
    cudaGetSymbolAddress((void**)&xh,  g_xh);
    cudaGetSymbolAddress((void**)&xl,  g_xl);
    cudaGetSymbolAddress((void**)&qh,  g_qh);
    cudaGetSymbolAddress((void**)&ql,  g_ql);
    cudaGetSymbolAddress((void**)&kh,  g_kh);
    cudaGetSymbolAddress((void**)&kl,  g_kl);
    cudaGetSymbolAddress((void**)&vh,  g_vh);
    cudaGetSymbolAddress((void**)&vl,  g_vl);
    cudaGetSymbolAddress((void**)&ch,  g_ch);
    cudaGetSymbolAddress((void**)&cl,  g_cl);
    cudaGetSymbolAddress((void**)&wqh, g_wqh);
    cudaGetSymbolAddress((void**)&wql, g_wql);
    cudaGetSymbolAddress((void**)&wkh, g_wkh);
    cudaGetSymbolAddress((void**)&wkl, g_wkl);
    cudaGetSymbolAddress((void**)&wvh, g_wvh);
    cudaGetSymbolAddress((void**)&wvl, g_wvl);
    cudaGetSymbolAddress((void**)&woh, g_woh);
    cudaGetSymbolAddress((void**)&wol, g_wol);

    split_all<<<XBLK + 4 * WBLK, 256>>>(
        (const float4*)x,  (uint2*)xh,  (uint2*)xl,
        (const float4*)wq, (uint2*)wqh, (uint2*)wql,
        (const float4*)wk, (uint2*)wkh, (uint2*)wkl,
        (const float4*)wv, (uint2*)wvh, (uint2*)wvl,
        (const float4*)wo, (uint2*)woh, (uint2*)wol);

    cudaFuncSetAttribute(gemm_qkv, cudaFuncAttributeMaxDynamicSharedMemorySize, GEMM_SMEM);
    cudaFuncSetAttribute(gemm_wo,  cudaFuncAttributeMaxDynamicSharedMemorySize, GEMM_SMEM);

    gemm_qkv<<<dim3(Ec / 128, NTOK / 128, 3), GTHR, GEMM_SMEM>>>(
        xh, xl, wqh, wql, wkh, wkl, wvh, wvl, qh, ql, kh, kl, vh, vl);

    cudaFuncSetAttribute(flash_attn_mma, cudaFuncAttributeMaxDynamicSharedMemorySize, FA_SMEM);
    flash_attn_mma<<<dim3(Sc / 64, Hc, Bc), 128, FA_SMEM>>>(qh, ql, kh, kl, vh, vl, ch, cl);

    gemm_wo<<<dim3(Ec / 128, NTOK / 128), GTHR, GEMM_SMEM>>>(ch, cl, woh, wol, out);
}